// round 1
// baseline (speedup 1.0000x reference)
#include <cuda_runtime.h>

#define BB 4
#define CC 256
#define SS 64
#define O3 192
#define DD 16
#define HH 64
#define WW 64
#define NN 65536
#define NSPLIT 32
#define NCHUNK (NN / NSPLIT)   // 2048

// ---- scratch (device globals; no cudaMalloc allowed) ----
__device__ float g_bcdt [(size_t)BB * O3 * NN];   // pre-conv  BCdt
__device__ float g_bcdt2[(size_t)BB * O3 * NN];   // post-conv BCdt
__device__ float g_ab   [(size_t)BB * SS * NN];   // softmax(dt) * B_
__device__ float g_hpart[(size_t)NSPLIT * BB * CC * SS];
__device__ float g_h4   [(size_t)BB * CC * SS];

// ============================================================
// K1: BCdt[b,o,n] = sum_c W_bcdt[o,c] * x[b,c,n] + b_bcdt[o]
//     block tile 64o x 128n, K chunks of 16; thread tile 8o x 4n
// ============================================================
__global__ __launch_bounds__(256) void k1_bcdt(
    const float* __restrict__ x, const float* __restrict__ Wb,
    const float* __restrict__ bb)
{
    __shared__ float sW[16][68];   // [kc][o], padded
    __shared__ float sX[16][128];  // [kc][n]

    const int b  = blockIdx.z;
    const int o0 = blockIdx.y * 64;
    const int n0 = blockIdx.x * 128;
    const int tid = threadIdx.x;
    const int og = tid >> 5;   // 0..7  (warp-uniform -> smem broadcast)
    const int ng = tid & 31;   // 0..31

    float acc[8][4];
#pragma unroll
    for (int i = 0; i < 8; i++)
#pragma unroll
        for (int j = 0; j < 4; j++) acc[i][j] = 0.f;

    const float* xb = x + (size_t)b * CC * NN;

    for (int c0 = 0; c0 < CC; c0 += 16) {
#pragma unroll
        for (int t = 0; t < 4; t++) {           // 64o x 16c
            int idx = tid + t * 256;
            int o = idx >> 4, kc = idx & 15;
            sW[kc][o] = Wb[(o0 + o) * CC + c0 + kc];
        }
#pragma unroll
        for (int t = 0; t < 8; t++) {           // 16c x 128n
            int idx = tid + t * 256;
            int kc = idx >> 7, nn = idx & 127;
            sX[kc][nn] = xb[(size_t)(c0 + kc) * NN + n0 + nn];
        }
        __syncthreads();
#pragma unroll
        for (int kc = 0; kc < 16; kc++) {
            float wr[8], xr[4];
#pragma unroll
            for (int i = 0; i < 8; i++) wr[i] = sW[kc][og * 8 + i];
#pragma unroll
            for (int j = 0; j < 4; j++) xr[j] = sX[kc][ng * 4 + j];
#pragma unroll
            for (int i = 0; i < 8; i++)
#pragma unroll
                for (int j = 0; j < 4; j++) acc[i][j] += wr[i] * xr[j];
        }
        __syncthreads();
    }
#pragma unroll
    for (int i = 0; i < 8; i++) {
        int o = o0 + og * 8 + i;
        float bias = bb[o];
        float* dst = g_bcdt + (size_t)(b * O3 + o) * NN + n0 + ng * 4;
#pragma unroll
        for (int j = 0; j < 4; j++) dst[j] = acc[i][j] + bias;
    }
}

// ============================================================
// K2: depthwise 3x3x3 conv (pad 1) per channel + b_dw
//     block = (64w x 4h), grid = (16 h-tiles, 16 d, B*192)
// ============================================================
__global__ __launch_bounds__(256) void k2_dwconv(
    const float* __restrict__ Wdw, const float* __restrict__ bdw)
{
    __shared__ float s_in[3][6][66];
    __shared__ float s_w[27];

    const int z  = blockIdx.z;          // b*192 + ch
    const int ch = z % O3;
    const int d  = blockIdx.y;
    const int h0 = blockIdx.x * 4;
    const int tid = threadIdx.x;
    const int tx = tid & 63, ty = tid >> 6;

    const float* in = g_bcdt + (size_t)z * NN;
    if (tid < 27) s_w[tid] = Wdw[ch * 27 + tid];

    for (int idx = tid; idx < 3 * 6 * 66; idx += 256) {
        int dd = idx / 396;
        int r  = idx % 396;
        int hh = r / 66, ww = r % 66;
        int gd = d + dd - 1, gh = h0 + hh - 1, gw = ww - 1;
        float v = 0.f;
        if (gd >= 0 && gd < DD && gh >= 0 && gh < HH && gw >= 0 && gw < WW)
            v = in[(size_t)gd * (HH * WW) + gh * WW + gw];
        s_in[dd][hh][ww] = v;
    }
    __syncthreads();

    float acc = bdw[ch];
#pragma unroll
    for (int kd = 0; kd < 3; kd++)
#pragma unroll
        for (int kh = 0; kh < 3; kh++)
#pragma unroll
            for (int kw = 0; kw < 3; kw++)
                acc += s_w[kd * 9 + kh * 3 + kw] * s_in[kd][ty + kh][tx + kw];

    g_bcdt2[(size_t)z * NN + (size_t)d * (HH * WW) + (h0 + ty) * WW + tx] = acc;
}

// ============================================================
// K3: AB[b,s,n] = softmax_n(dt[b,s,:])[n] * B_[b,s,n]
//     (the +A[s] shift cancels in softmax)  one block per (b,s) row
// ============================================================
__global__ __launch_bounds__(256) void k3_softmax_ab()
{
    const int bs = blockIdx.x;
    const int b = bs >> 6, s = bs & 63;
    const float4* dt   = (const float4*)(g_bcdt2 + (size_t)(b * O3 + 128 + s) * NN);
    const float4* Brow = (const float4*)(g_bcdt2 + (size_t)(b * O3 + s) * NN);
    float4* ab = (float4*)(g_ab + (size_t)(b * SS + s) * NN);
    const int tid = threadIdx.x;
    __shared__ float red[256];

    // pass 1: max
    float m = -1e30f;
    for (int i = tid; i < NN / 4; i += 256) {
        float4 v = dt[i];
        m = fmaxf(m, fmaxf(fmaxf(v.x, v.y), fmaxf(v.z, v.w)));
    }
    red[tid] = m; __syncthreads();
    for (int off = 128; off > 0; off >>= 1) {
        if (tid < off) red[tid] = fmaxf(red[tid], red[tid + off]);
        __syncthreads();
    }
    m = red[0]; __syncthreads();

    // pass 2: sum of exp
    float sum = 0.f;
    for (int i = tid; i < NN / 4; i += 256) {
        float4 v = dt[i];
        sum += expf(v.x - m) + expf(v.y - m) + expf(v.z - m) + expf(v.w - m);
    }
    red[tid] = sum; __syncthreads();
    for (int off = 128; off > 0; off >>= 1) {
        if (tid < off) red[tid] += red[tid + off];
        __syncthreads();
    }
    const float inv = 1.f / red[0];
    __syncthreads();

    // pass 3: AB = softmax * B_
    for (int i = tid; i < NN / 4; i += 256) {
        float4 v = dt[i];
        float4 bv = Brow[i];
        float4 o;
        o.x = expf(v.x - m) * inv * bv.x;
        o.y = expf(v.y - m) * inv * bv.y;
        o.z = expf(v.z - m) * inv * bv.z;
        o.w = expf(v.w - m) * inv * bv.w;
        ab[i] = o;
    }
}

// ============================================================
// K4: split-K partials of h[b,c,s] = sum_n x[b,c,n]*AB[b,s,n]
//     block tile 128c x 64s over one 2048-n chunk; thread 16c x 2s
// ============================================================
__global__ __launch_bounds__(256) void k4_h_partial(const float* __restrict__ x)
{
    __shared__ float xs[32][129];   // [kn][c]
    __shared__ float as[32][65];    // [kn][s]

    const int split = blockIdx.x;
    const int c0 = blockIdx.y * 128;
    const int b  = blockIdx.z;
    const int nbase = split * NCHUNK;
    const int tid = threadIdx.x;
    const int cg = tid >> 5;   // 0..7  -> 16 c each (warp-uniform)
    const int sg = tid & 31;   // 0..31 ->  2 s each

    float acc[16][2];
#pragma unroll
    for (int i = 0; i < 16; i++) { acc[i][0] = 0.f; acc[i][1] = 0.f; }

    const float* xb  = x + ((size_t)b * CC + c0) * NN;
    const float* abb = g_ab + (size_t)b * SS * NN;

    for (int n0 = nbase; n0 < nbase + NCHUNK; n0 += 32) {
#pragma unroll
        for (int t = 0; t < 16; t++) {          // 128c x 32n -> xs[n][c]
            int idx = tid + t * 256;
            int c = idx >> 5, kn = idx & 31;
            xs[kn][c] = xb[(size_t)c * NN + n0 + kn];
        }
#pragma unroll
        for (int t = 0; t < 8; t++) {           // 64s x 32n -> as[n][s]
            int idx = tid + t * 256;
            int s = idx >> 5, kn = idx & 31;
            as[kn][s] = abb[(size_t)s * NN + n0 + kn];
        }
        __syncthreads();
#pragma unroll
        for (int kn = 0; kn < 32; kn++) {
            float xr[16], ar[2];
#pragma unroll
            for (int i = 0; i < 16; i++) xr[i] = xs[kn][cg * 16 + i];
            ar[0] = as[kn][sg * 2 + 0];
            ar[1] = as[kn][sg * 2 + 1];
#pragma unroll
            for (int i = 0; i < 16; i++) {
                acc[i][0] += xr[i] * ar[0];
                acc[i][1] += xr[i] * ar[1];
            }
        }
        __syncthreads();
    }

    float* dst = g_hpart + (size_t)split * BB * CC * SS;
#pragma unroll
    for (int i = 0; i < 16; i++) {
        size_t base = (size_t)(b * CC + c0 + cg * 16 + i) * SS + sg * 2;
        dst[base + 0] = acc[i][0];
        dst[base + 1] = acc[i][1];
    }
}

// ============================================================
// K5: reduce partials -> h; hz = W_hz@h + b_hz; h3 = h2*(silu(z)+Dp);
//     h4 = W_out@h3 + b_out. One block per (b,s) column.
// ============================================================
__global__ __launch_bounds__(256) void k5_small(
    const float* __restrict__ Whz, const float* __restrict__ bhz,
    const float* __restrict__ Wout, const float* __restrict__ bout,
    const float* __restrict__ Dp, float* __restrict__ outh4)
{
    const int bs = blockIdx.x;
    const int b = bs >> 6, s = bs & 63;
    const int tid = threadIdx.x;
    __shared__ float sh[256];
    __shared__ float sh3[256];

    float a = 0.f;
    for (int k = 0; k < NSPLIT; k++)
        a += g_hpart[(size_t)k * BB * CC * SS + (size_t)(b * CC + tid) * SS + s];
    sh[tid] = a;
    __syncthreads();

    float a0 = bhz[tid];
    float a1 = bhz[256 + tid];
    for (int c = 0; c < 256; c++) {
        float hv = sh[c];
        a0 += Whz[tid * 256 + c] * hv;
        a1 += Whz[(256 + tid) * 256 + c] * hv;
    }
    float sig = 1.f / (1.f + expf(-a1));
    sh3[tid] = a0 * (a1 * sig + Dp[0]);
    __syncthreads();

    float a2 = bout[tid];
    for (int c = 0; c < 256; c++) a2 += Wout[tid * 256 + c] * sh3[c];

    size_t oi = (size_t)(b * CC + tid) * SS + s;
    g_h4[oi] = a2;
    outh4[oi] = a2;
}

// ============================================================
// K6: y[b,o,n] = sum_s h4[b,o,s] * C_[b,s,n]
//     block tile 64o x 128n, K = 64 in chunks of 16; thread 8o x 4n
// ============================================================
__global__ __launch_bounds__(256) void k6_y(float* __restrict__ y)
{
    __shared__ float sh4t[64][65];  // [s][o]
    __shared__ float sC[16][128];   // [ks][n]

    const int b  = blockIdx.z;
    const int o0 = blockIdx.y * 64;
    const int n0 = blockIdx.x * 128;
    const int tid = threadIdx.x;
    const int og = tid >> 5;   // warp-uniform
    const int ng = tid & 31;

#pragma unroll
    for (int t = 0; t < 16; t++) {              // 64o x 64s -> sh4t[s][o]
        int idx = tid + t * 256;
        int o = idx >> 6, s = idx & 63;
        sh4t[s][o] = g_h4[(size_t)(b * CC + o0 + o) * SS + s];
    }

    float acc[8][4];
#pragma unroll
    for (int i = 0; i < 8; i++)
#pragma unroll
        for (int j = 0; j < 4; j++) acc[i][j] = 0.f;

    const float* Cb = g_bcdt2 + (size_t)(b * O3 + 64) * NN;  // C_ channels 64..127

    for (int s0 = 0; s0 < SS; s0 += 16) {
#pragma unroll
        for (int t = 0; t < 8; t++) {           // 16s x 128n
            int idx = tid + t * 256;
            int ks = idx >> 7, nn = idx & 127;
            sC[ks][nn] = Cb[(size_t)(s0 + ks) * NN + n0 + nn];
        }
        __syncthreads();
#pragma unroll
        for (int ks = 0; ks < 16; ks++) {
            float wr[8], cr[4];
#pragma unroll
            for (int i = 0; i < 8; i++) wr[i] = sh4t[s0 + ks][og * 8 + i];
#pragma unroll
            for (int j = 0; j < 4; j++) cr[j] = sC[ks][ng * 4 + j];
#pragma unroll
            for (int i = 0; i < 8; i++)
#pragma unroll
                for (int j = 0; j < 4; j++) acc[i][j] += wr[i] * cr[j];
        }
        __syncthreads();
    }

#pragma unroll
    for (int i = 0; i < 8; i++) {
        float* dst = y + (size_t)(b * CC + o0 + og * 8 + i) * NN + n0 + ng * 4;
#pragma unroll
        for (int j = 0; j < 4; j++) dst[j] = acc[i][j];
    }
}

// ============================================================
extern "C" void kernel_launch(void* const* d_in, const int* in_sizes, int n_in,
                              void* d_out, int out_size)
{
    const float* x      = (const float*)d_in[0];
    const float* W_bcdt = (const float*)d_in[1];
    const float* b_bcdt = (const float*)d_in[2];
    const float* W_dw   = (const float*)d_in[3];
    const float* b_dw   = (const float*)d_in[4];
    const float* W_hz   = (const float*)d_in[5];
    const float* b_hz   = (const float*)d_in[6];
    const float* W_out  = (const float*)d_in[7];
    const float* b_out  = (const float*)d_in[8];
    // d_in[9] = A : softmax shift-invariant, mathematically cancels
    const float* Dp     = (const float*)d_in[10];
    float* out = (float*)d_out;
    float* out_h4 = out + (size_t)BB * CC * NN;   // y (B,C,D,H,W) then h4 (B,C,S)

    k1_bcdt     <<<dim3(NN / 128, O3 / 64, BB), 256>>>(x, W_bcdt, b_bcdt);
    k2_dwconv   <<<dim3(HH / 4, DD, BB * O3), 256>>>(W_dw, b_dw);
    k3_softmax_ab<<<BB * SS, 256>>>();
    k4_h_partial<<<dim3(NSPLIT, CC / 128, BB), 256>>>(x);
    k5_small    <<<BB * SS, 256>>>(W_hz, b_hz, W_out, b_out, Dp, out_h4);
    k6_y        <<<dim3(NN / 128, CC / 64, BB), 256>>>(out);
}

// round 4
// speedup vs baseline: 1.6118x; 1.6118x over previous
#include <cuda_runtime.h>

#define BB 4
#define CC 256
#define SS 64
#define O3 192
#define DD 16
#define HH 64
#define WW 64
#define NN 65536
#define NSPLIT 64
#define NCHUNK (NN / NSPLIT)   // 1024

// ---- scratch (device globals; no cudaMalloc allowed) ----
__device__ float g_bcdt [(size_t)BB * O3 * NN];   // pre-conv  BCdt
__device__ float g_bcdt2[(size_t)BB * O3 * NN];   // post-conv BCdt
__device__ float g_ab   [(size_t)BB * SS * NN];   // softmax(dt) * B_
__device__ float g_hpart[(size_t)NSPLIT * BB * CC * SS];
__device__ float g_h4   [(size_t)BB * CC * SS];

// ---- tf32 helpers ----
__device__ __forceinline__ unsigned f2tf32(float f) {
    unsigned r;
    asm("cvt.rna.tf32.f32 %0, %1;" : "=r"(r) : "f"(f));
    return r;
}
__device__ __forceinline__ void mma_tf32(float c[4], const unsigned a[4], const unsigned b[2]) {
    asm volatile(
        "mma.sync.aligned.m16n8k8.row.col.f32.tf32.tf32.f32 "
        "{%0,%1,%2,%3}, {%4,%5,%6,%7}, {%8,%9}, {%0,%1,%2,%3};"
        : "+f"(c[0]), "+f"(c[1]), "+f"(c[2]), "+f"(c[3])
        : "r"(a[0]), "r"(a[1]), "r"(a[2]), "r"(a[3]), "r"(b[0]), "r"(b[1]));
}

// ============================================================
// T1: BCdt = W_bcdt(192x256) @ x(256x65536) + bias   (tf32 MMA)
//     block tile 64o x 128n, K-chunk 16, double buffered
// ============================================================
__global__ __launch_bounds__(256) void t1_bcdt(
    const float* __restrict__ x, const float* __restrict__ Wb,
    const float* __restrict__ bb)
{
    __shared__ unsigned sA[2][16][72];   // [stage][k][o]
    __shared__ unsigned sB[2][16][136];  // [stage][k][n]

    const int b  = blockIdx.z;
    const int o0 = blockIdx.y * 64;
    const int n0 = blockIdx.x * 128;
    const int tid  = threadIdx.x;
    const int warp = tid >> 5, lane = tid & 31;
    const int wm = warp >> 2, wn = warp & 3;     // 2 x 4 warp grid
    const int gid = lane >> 2, tig = lane & 3;

    const float* xb = x + (size_t)b * CC * NN;

    float acc[2][4][4];
#pragma unroll
    for (int i = 0; i < 2; i++)
#pragma unroll
        for (int j = 0; j < 4; j++)
#pragma unroll
            for (int k = 0; k < 4; k++) acc[i][j][k] = 0.f;

    const int ao = tid >> 2, akq = tid & 3;      // A mapping (1 float4/thread)
    float4 ra, rb0, rb1;

    auto ldg = [&](int c0) {
        ra  = *(const float4*)&Wb[(o0 + ao) * CC + c0 + akq * 4];
        rb0 = *(const float4*)&xb[(size_t)(c0 + (tid >> 5)) * NN + n0 + (tid & 31) * 4];
        int i1 = tid + 256;
        rb1 = *(const float4*)&xb[(size_t)(c0 + (i1 >> 5)) * NN + n0 + (i1 & 31) * 4];
    };
    auto sts = [&](int st) {
        sA[st][akq * 4 + 0][ao] = f2tf32(ra.x);
        sA[st][akq * 4 + 1][ao] = f2tf32(ra.y);
        sA[st][akq * 4 + 2][ao] = f2tf32(ra.z);
        sA[st][akq * 4 + 3][ao] = f2tf32(ra.w);
        unsigned* p0 = &sB[st][tid >> 5][(tid & 31) * 4];
        p0[0] = f2tf32(rb0.x); p0[1] = f2tf32(rb0.y);
        p0[2] = f2tf32(rb0.z); p0[3] = f2tf32(rb0.w);
        int i1 = tid + 256;
        unsigned* p1 = &sB[st][i1 >> 5][(i1 & 31) * 4];
        p1[0] = f2tf32(rb1.x); p1[1] = f2tf32(rb1.y);
        p1[2] = f2tf32(rb1.z); p1[3] = f2tf32(rb1.w);
    };
    auto compute = [&](int st) {
#pragma unroll
        for (int ks = 0; ks < 2; ks++) {
            unsigned afr[2][4], bfr[4][2];
#pragma unroll
            for (int mt = 0; mt < 2; mt++) {
                int m = wm * 32 + mt * 16 + gid;
                afr[mt][0] = sA[st][ks * 8 + tig][m];
                afr[mt][1] = sA[st][ks * 8 + tig][m + 8];
                afr[mt][2] = sA[st][ks * 8 + tig + 4][m];
                afr[mt][3] = sA[st][ks * 8 + tig + 4][m + 8];
            }
#pragma unroll
            for (int nt = 0; nt < 4; nt++) {
                int n = wn * 32 + nt * 8 + gid;
                bfr[nt][0] = sB[st][ks * 8 + tig][n];
                bfr[nt][1] = sB[st][ks * 8 + tig + 4][n];
            }
#pragma unroll
            for (int mt = 0; mt < 2; mt++)
#pragma unroll
                for (int nt = 0; nt < 4; nt++)
                    mma_tf32(acc[mt][nt], afr[mt], bfr[nt]);
        }
    };

    ldg(0); sts(0); __syncthreads();
#pragma unroll 1
    for (int ch = 0; ch < 16; ch++) {
        int st = ch & 1;
        if (ch < 15) ldg((ch + 1) * 16);
        compute(st);
        if (ch < 15) sts(st ^ 1);
        __syncthreads();
    }

#pragma unroll
    for (int mt = 0; mt < 2; mt++) {
        int o = o0 + wm * 32 + mt * 16 + gid;
        float bi0 = bb[o], bi1 = bb[o + 8];
#pragma unroll
        for (int nt = 0; nt < 4; nt++) {
            int n = n0 + wn * 32 + nt * 8 + tig * 2;
            float2 v0 = {acc[mt][nt][0] + bi0, acc[mt][nt][1] + bi0};
            float2 v1 = {acc[mt][nt][2] + bi1, acc[mt][nt][3] + bi1};
            *(float2*)&g_bcdt[(size_t)(b * O3 + o) * NN + n] = v0;
            *(float2*)&g_bcdt[(size_t)(b * O3 + o + 8) * NN + n] = v1;
        }
    }
}

// ============================================================
// K2: depthwise 3x3x3 conv (pad 1) + b_dw   (unchanged)
// ============================================================
__global__ __launch_bounds__(256) void k2_dwconv(
    const float* __restrict__ Wdw, const float* __restrict__ bdw)
{
    __shared__ float s_in[3][6][66];
    __shared__ float s_w[27];

    const int z  = blockIdx.z;
    const int ch = z % O3;
    const int d  = blockIdx.y;
    const int h0 = blockIdx.x * 4;
    const int tid = threadIdx.x;
    const int tx = tid & 63, ty = tid >> 6;

    const float* in = g_bcdt + (size_t)z * NN;
    if (tid < 27) s_w[tid] = Wdw[ch * 27 + tid];

    for (int idx = tid; idx < 3 * 6 * 66; idx += 256) {
        int dd = idx / 396;
        int r  = idx % 396;
        int hh = r / 66, ww = r % 66;
        int gd = d + dd - 1, gh = h0 + hh - 1, gw = ww - 1;
        float v = 0.f;
        if (gd >= 0 && gd < DD && gh >= 0 && gh < HH && gw >= 0 && gw < WW)
            v = in[(size_t)gd * (HH * WW) + gh * WW + gw];
        s_in[dd][hh][ww] = v;
    }
    __syncthreads();

    float acc = bdw[ch];
#pragma unroll
    for (int kd = 0; kd < 3; kd++)
#pragma unroll
        for (int kh = 0; kh < 3; kh++)
#pragma unroll
            for (int kw = 0; kw < 3; kw++)
                acc += s_w[kd * 9 + kh * 3 + kw] * s_in[kd][ty + kh][tx + kw];

    g_bcdt2[(size_t)z * NN + (size_t)d * (HH * WW) + (h0 + ty) * WW + tx] = acc;
}

// ============================================================
// K3: AB = softmax_n(dt) * B_   (+A[s] cancels)   (unchanged)
// ============================================================
__global__ __launch_bounds__(256) void k3_softmax_ab()
{
    const int bs = blockIdx.x;
    const int b = bs >> 6, s = bs & 63;
    const float4* dt   = (const float4*)(g_bcdt2 + (size_t)(b * O3 + 128 + s) * NN);
    const float4* Brow = (const float4*)(g_bcdt2 + (size_t)(b * O3 + s) * NN);
    float4* ab = (float4*)(g_ab + (size_t)(b * SS + s) * NN);
    const int tid = threadIdx.x;
    __shared__ float red[256];

    float m = -1e30f;
    for (int i = tid; i < NN / 4; i += 256) {
        float4 v = dt[i];
        m = fmaxf(m, fmaxf(fmaxf(v.x, v.y), fmaxf(v.z, v.w)));
    }
    red[tid] = m; __syncthreads();
    for (int off = 128; off > 0; off >>= 1) {
        if (tid < off) red[tid] = fmaxf(red[tid], red[tid + off]);
        __syncthreads();
    }
    m = red[0]; __syncthreads();

    float sum = 0.f;
    for (int i = tid; i < NN / 4; i += 256) {
        float4 v = dt[i];
        sum += expf(v.x - m) + expf(v.y - m) + expf(v.z - m) + expf(v.w - m);
    }
    red[tid] = sum; __syncthreads();
    for (int off = 128; off > 0; off >>= 1) {
        if (tid < off) red[tid] += red[tid + off];
        __syncthreads();
    }
    const float inv = 1.f / red[0];
    __syncthreads();

    for (int i = tid; i < NN / 4; i += 256) {
        float4 v = dt[i];
        float4 bv = Brow[i];
        float4 o;
        o.x = expf(v.x - m) * inv * bv.x;
        o.y = expf(v.y - m) * inv * bv.y;
        o.z = expf(v.z - m) * inv * bv.z;
        o.w = expf(v.w - m) * inv * bv.w;
        ab[i] = o;
    }
}

// ============================================================
// T4: split-K partials of h[b,c,s] = sum_n x[b,c,n]*AB[b,s,n]
//     tf32 MMA, block tile 128c x 64s, K-chunk 16, double buffered
// ============================================================
__global__ __launch_bounds__(256) void t4_h_partial(const float* __restrict__ x)
{
    __shared__ unsigned sA[2][16][136];  // [stage][k][c]
    __shared__ unsigned sB[2][16][72];   // [stage][k][s]

    const int split = blockIdx.x;
    const int cbase = blockIdx.y * 128;
    const int b     = blockIdx.z;
    const int nbase = split * NCHUNK;
    const int tid  = threadIdx.x;
    const int warp = tid >> 5, lane = tid & 31;
    const int wm = warp >> 1, wn = warp & 1;     // 4 x 2 warp grid
    const int gid = lane >> 2, tig = lane & 3;

    const float* xb  = x + (size_t)b * CC * NN;
    const float* abb = g_ab + (size_t)b * SS * NN;

    float acc[2][4][4];
#pragma unroll
    for (int i = 0; i < 2; i++)
#pragma unroll
        for (int j = 0; j < 4; j++)
#pragma unroll
            for (int k = 0; k < 4; k++) acc[i][j][k] = 0.f;

    const int ac0 = tid >> 2, akq = tid & 3;         // A idx (t=0), +64 c for t=1
    const int bs_ = tid >> 2, bkq = tid & 3;         // B idx
    float4 ra0, ra1, rb;

    auto ldg = [&](int k0) {
        ra0 = *(const float4*)&xb[(size_t)(cbase + ac0) * NN + nbase + k0 + akq * 4];
        ra1 = *(const float4*)&xb[(size_t)(cbase + 64 + ac0) * NN + nbase + k0 + akq * 4];
        rb  = *(const float4*)&abb[(size_t)bs_ * NN + nbase + k0 + bkq * 4];
    };
    auto sts = [&](int st) {
        sA[st][akq * 4 + 0][ac0] = f2tf32(ra0.x);
        sA[st][akq * 4 + 1][ac0] = f2tf32(ra0.y);
        sA[st][akq * 4 + 2][ac0] = f2tf32(ra0.z);
        sA[st][akq * 4 + 3][ac0] = f2tf32(ra0.w);
        sA[st][akq * 4 + 0][64 + ac0] = f2tf32(ra1.x);
        sA[st][akq * 4 + 1][64 + ac0] = f2tf32(ra1.y);
        sA[st][akq * 4 + 2][64 + ac0] = f2tf32(ra1.z);
        sA[st][akq * 4 + 3][64 + ac0] = f2tf32(ra1.w);
        sB[st][bkq * 4 + 0][bs_] = f2tf32(rb.x);
        sB[st][bkq * 4 + 1][bs_] = f2tf32(rb.y);
        sB[st][bkq * 4 + 2][bs_] = f2tf32(rb.z);
        sB[st][bkq * 4 + 3][bs_] = f2tf32(rb.w);
    };
    auto compute = [&](int st) {
#pragma unroll
        for (int ks = 0; ks < 2; ks++) {
            unsigned afr[2][4], bfr[4][2];
#pragma unroll
            for (int mt = 0; mt < 2; mt++) {
                int m = wm * 32 + mt * 16 + gid;
                afr[mt][0] = sA[st][ks * 8 + tig][m];
                afr[mt][1] = sA[st][ks * 8 + tig][m + 8];
                afr[mt][2] = sA[st][ks * 8 + tig + 4][m];
                afr[mt][3] = sA[st][ks * 8 + tig + 4][m + 8];
            }
#pragma unroll
            for (int nt = 0; nt < 4; nt++) {
                int n = wn * 32 + nt * 8 + gid;
                bfr[nt][0] = sB[st][ks * 8 + tig][n];
                bfr[nt][1] = sB[st][ks * 8 + tig + 4][n];
            }
#pragma unroll
            for (int mt = 0; mt < 2; mt++)
#pragma unroll
                for (int nt = 0; nt < 4; nt++)
                    mma_tf32(acc[mt][nt], afr[mt], bfr[nt]);
        }
    };

    ldg(0); sts(0); __syncthreads();
    const int NCH = NCHUNK / 16;
#pragma unroll 1
    for (int ch = 0; ch < NCH; ch++) {
        int st = ch & 1;
        if (ch < NCH - 1) ldg((ch + 1) * 16);
        compute(st);
        if (ch < NCH - 1) sts(st ^ 1);
        __syncthreads();
    }

    float* dst = g_hpart + (size_t)split * (BB * CC * SS);
#pragma unroll
    for (int mt = 0; mt < 2; mt++) {
        int c = cbase + wm * 32 + mt * 16 + gid;
#pragma unroll
        for (int nt = 0; nt < 4; nt++) {
            int s = wn * 32 + nt * 8 + tig * 2;
            float2 v0 = {acc[mt][nt][0], acc[mt][nt][1]};
            float2 v1 = {acc[mt][nt][2], acc[mt][nt][3]};
            *(float2*)&dst[(size_t)(b * CC + c) * SS + s] = v0;
            *(float2*)&dst[(size_t)(b * CC + c + 8) * SS + s] = v1;
        }
    }
}

// ============================================================
// K5: reduce partials -> h; MLP chain -> h4   (NSPLIT=64)
// ============================================================
__global__ __launch_bounds__(256) void k5_small(
    const float* __restrict__ Whz, const float* __restrict__ bhz,
    const float* __restrict__ Wout, const float* __restrict__ bout,
    const float* __restrict__ Dp, float* __restrict__ outh4)
{
    const int bs = blockIdx.x;
    const int b = bs >> 6, s = bs & 63;
    const int tid = threadIdx.x;
    __shared__ float sh[256];
    __shared__ float sh3[256];

    float a = 0.f;
    for (int k = 0; k < NSPLIT; k++)
        a += g_hpart[(size_t)k * BB * CC * SS + (size_t)(b * CC + tid) * SS + s];
    sh[tid] = a;
    __syncthreads();

    float a0 = bhz[tid];
    float a1 = bhz[256 + tid];
    for (int c = 0; c < 256; c++) {
        float hv = sh[c];
        a0 += Whz[tid * 256 + c] * hv;
        a1 += Whz[(256 + tid) * 256 + c] * hv;
    }
    float sig = 1.f / (1.f + expf(-a1));
    sh3[tid] = a0 * (a1 * sig + Dp[0]);
    __syncthreads();

    float a2 = bout[tid];
    for (int c = 0; c < 256; c++) a2 += Wout[tid * 256 + c] * sh3[c];

    size_t oi = (size_t)(b * CC + tid) * SS + s;
    g_h4[oi] = a2;
    outh4[oi] = a2;
}

// ============================================================
// T6: y = h4(256x64) @ C_(64x65536)   (tf32 MMA)
//     block tile 64o x 128n, K = 64 in chunks of 16
// ============================================================
__global__ __launch_bounds__(256) void t6_y(float* __restrict__ y)
{
    __shared__ unsigned sA[2][16][72];   // [stage][k][o]
    __shared__ unsigned sB[2][16][136];  // [stage][k][n]

    const int b  = blockIdx.z;
    const int o0 = blockIdx.y * 64;
    const int n0 = blockIdx.x * 128;
    const int tid  = threadIdx.x;
    const int warp = tid >> 5, lane = tid & 31;
    const int wm = warp >> 2, wn = warp & 3;
    const int gid = lane >> 2, tig = lane & 3;

    const float* Cb = g_bcdt2 + (size_t)(b * O3 + 64) * NN;
    const float* h4b = g_h4 + (size_t)b * CC * SS;

    float acc[2][4][4];
#pragma unroll
    for (int i = 0; i < 2; i++)
#pragma unroll
        for (int j = 0; j < 4; j++)
#pragma unroll
            for (int k = 0; k < 4; k++) acc[i][j][k] = 0.f;

    const int ao = tid >> 2, akq = tid & 3;
    float4 ra, rb0, rb1;

    auto ldg = [&](int s0) {
        ra  = *(const float4*)&h4b[(o0 + ao) * SS + s0 + akq * 4];
        rb0 = *(const float4*)&Cb[(size_t)(s0 + (tid >> 5)) * NN + n0 + (tid & 31) * 4];
        int i1 = tid + 256;
        rb1 = *(const float4*)&Cb[(size_t)(s0 + (i1 >> 5)) * NN + n0 + (i1 & 31) * 4];
    };
    auto sts = [&](int st) {
        sA[st][akq * 4 + 0][ao] = f2tf32(ra.x);
        sA[st][akq * 4 + 1][ao] = f2tf32(ra.y);
        sA[st][akq * 4 + 2][ao] = f2tf32(ra.z);
        sA[st][akq * 4 + 3][ao] = f2tf32(ra.w);
        unsigned* p0 = &sB[st][tid >> 5][(tid & 31) * 4];
        p0[0] = f2tf32(rb0.x); p0[1] = f2tf32(rb0.y);
        p0[2] = f2tf32(rb0.z); p0[3] = f2tf32(rb0.w);
        int i1 = tid + 256;
        unsigned* p1 = &sB[st][i1 >> 5][(i1 & 31) * 4];
        p1[0] = f2tf32(rb1.x); p1[1] = f2tf32(rb1.y);
        p1[2] = f2tf32(rb1.z); p1[3] = f2tf32(rb1.w);
    };
    auto compute = [&](int st) {
#pragma unroll
        for (int ks = 0; ks < 2; ks++) {
            unsigned afr[2][4], bfr[4][2];
#pragma unroll
            for (int mt = 0; mt < 2; mt++) {
                int m = wm * 32 + mt * 16 + gid;
                afr[mt][0] = sA[st][ks * 8 + tig][m];
                afr[mt][1] = sA[st][ks * 8 + tig][m + 8];
                afr[mt][2] = sA[st][ks * 8 + tig + 4][m];
                afr[mt][3] = sA[st][ks * 8 + tig + 4][m + 8];
            }
#pragma unroll
            for (int nt = 0; nt < 4; nt++) {
                int n = wn * 32 + nt * 8 + gid;
                bfr[nt][0] = sB[st][ks * 8 + tig][n];
                bfr[nt][1] = sB[st][ks * 8 + tig + 4][n];
            }
#pragma unroll
            for (int mt = 0; mt < 2; mt++)
#pragma unroll
                for (int nt = 0; nt < 4; nt++)
                    mma_tf32(acc[mt][nt], afr[mt], bfr[nt]);
        }
    };

    ldg(0); sts(0); __syncthreads();
#pragma unroll 1
    for (int ch = 0; ch < 4; ch++) {
        int st = ch & 1;
        if (ch < 3) ldg((ch + 1) * 16);
        compute(st);
        if (ch < 3) sts(st ^ 1);
        __syncthreads();
    }

#pragma unroll
    for (int mt = 0; mt < 2; mt++) {
        int o = o0 + wm * 32 + mt * 16 + gid;
#pragma unroll
        for (int nt = 0; nt < 4; nt++) {
            int n = n0 + wn * 32 + nt * 8 + tig * 2;
            float2 v0 = {acc[mt][nt][0], acc[mt][nt][1]};
            float2 v1 = {acc[mt][nt][2], acc[mt][nt][3]};
            *(float2*)&y[(size_t)(b * CC + o) * NN + n] = v0;
            *(float2*)&y[(size_t)(b * CC + o + 8) * NN + n] = v1;
        }
    }
}

// ============================================================
extern "C" void kernel_launch(void* const* d_in, const int* in_sizes, int n_in,
                              void* d_out, int out_size)
{
    const float* x      = (const float*)d_in[0];
    const float* W_bcdt = (const float*)d_in[1];
    const float* b_bcdt = (const float*)d_in[2];
    const float* W_dw   = (const float*)d_in[3];
    const float* b_dw   = (const float*)d_in[4];
    const float* W_hz   = (const float*)d_in[5];
    const float* b_hz   = (const float*)d_in[6];
    const float* W_out  = (const float*)d_in[7];
    const float* b_out  = (const float*)d_in[8];
    // d_in[9] = A : softmax shift-invariant, cancels exactly
    const float* Dp     = (const float*)d_in[10];
    float* out = (float*)d_out;
    float* out_h4 = out + (size_t)BB * CC * NN;   // y (B,C,D,H,W) then h4 (B,C,S)

    t1_bcdt      <<<dim3(NN / 128, O3 / 64, BB), 256>>>(x, W_bcdt, b_bcdt);
    k2_dwconv    <<<dim3(HH / 4, DD, BB * O3), 256>>>(W_dw, b_dw);
    k3_softmax_ab<<<BB * SS, 256>>>();
    t4_h_partial <<<dim3(NSPLIT, CC / 128, BB), 256>>>(x);
    k5_small     <<<BB * SS, 256>>>(W_hz, b_hz, W_out, b_out, Dp, out_h4);
    t6_y         <<<dim3(NN / 128, CC / 64, BB), 256>>>(out);
}

// round 8
// speedup vs baseline: 2.0381x; 1.2646x over previous
#include <cuda_runtime.h>

#define BB 4
#define CC 256
#define SS 64
#define O3 192
#define DD 16
#define HH 64
#define WW 64
#define NN 65536
#define NSPLIT 64
#define NCHUNK (NN / NSPLIT)   // 1024

// ---- scratch (device globals; no cudaMalloc allowed) ----
__device__ float g_bcdt [(size_t)BB * O3 * NN];   // pre-conv  BCdt
__device__ float g_bcdt2[(size_t)BB * O3 * NN];   // post-conv BCdt
__device__ float g_ab   [(size_t)BB * SS * NN];   // softmax(dt) * B_
__device__ float g_hpart[(size_t)NSPLIT * BB * CC * SS];
__device__ float g_h4   [(size_t)BB * CC * SS];

// ---- tf32 helpers ----
__device__ __forceinline__ unsigned f2tf32(float f) {
    unsigned r;
    asm("cvt.rna.tf32.f32 %0, %1;" : "=r"(r) : "f"(f));
    return r;
}
__device__ __forceinline__ void mma_tf32(float c[4], const unsigned a[4], const unsigned b[2]) {
    asm volatile(
        "mma.sync.aligned.m16n8k8.row.col.f32.tf32.tf32.f32 "
        "{%0,%1,%2,%3}, {%4,%5,%6,%7}, {%8,%9}, {%0,%1,%2,%3};"
        : "+f"(c[0]), "+f"(c[1]), "+f"(c[2]), "+f"(c[3])
        : "r"(a[0]), "r"(a[1]), "r"(a[2]), "r"(a[3]), "r"(b[0]), "r"(b[1]));
}
// physical-column swizzle for k-major staging (kills 4-way STS conflicts;
// per-instruction-uniform on the LDS side so fragment loads stay clean)
#define SWZ(col, k) ((col) ^ ((((k) >> 2) & 3) << 3))

// ============================================================
// T1: BCdt = W_bcdt(192x256) @ x(256x65536) + bias   (tf32 MMA)
// ============================================================
__global__ __launch_bounds__(256) void t1_bcdt(
    const float* __restrict__ x, const float* __restrict__ Wb,
    const float* __restrict__ bb)
{
    __shared__ unsigned sA[2][16][72];   // [stage][k][o], swizzled cols
    __shared__ unsigned sB[2][16][136];  // [stage][k][n]

    const int b  = blockIdx.z;
    const int o0 = blockIdx.y * 64;
    const int n0 = blockIdx.x * 128;
    const int tid  = threadIdx.x;
    const int warp = tid >> 5, lane = tid & 31;
    const int wm = warp >> 2, wn = warp & 3;     // 2 x 4 warp grid
    const int gid = lane >> 2, tig = lane & 3;

    const float* xb = x + (size_t)b * CC * NN;

    float acc[2][4][4];
#pragma unroll
    for (int i = 0; i < 2; i++)
#pragma unroll
        for (int j = 0; j < 4; j++)
#pragma unroll
            for (int k = 0; k < 4; k++) acc[i][j][k] = 0.f;

    const int ao = tid >> 2, akq = tid & 3;
    const int colA = ao ^ (akq << 3);            // SWZ for rows akq*4+i (i<4)
    float4 ra, rb0, rb1;

    auto ldg = [&](int c0) {
        ra  = *(const float4*)&Wb[(o0 + ao) * CC + c0 + akq * 4];
        rb0 = *(const float4*)&xb[(size_t)(c0 + (tid >> 5)) * NN + n0 + (tid & 31) * 4];
        int i1 = tid + 256;
        rb1 = *(const float4*)&xb[(size_t)(c0 + (i1 >> 5)) * NN + n0 + (i1 & 31) * 4];
    };
    auto sts = [&](int st) {
        sA[st][akq * 4 + 0][colA] = f2tf32(ra.x);
        sA[st][akq * 4 + 1][colA] = f2tf32(ra.y);
        sA[st][akq * 4 + 2][colA] = f2tf32(ra.z);
        sA[st][akq * 4 + 3][colA] = f2tf32(ra.w);
        unsigned* p0 = &sB[st][tid >> 5][(tid & 31) * 4];
        p0[0] = f2tf32(rb0.x); p0[1] = f2tf32(rb0.y);
        p0[2] = f2tf32(rb0.z); p0[3] = f2tf32(rb0.w);
        int i1 = tid + 256;
        unsigned* p1 = &sB[st][i1 >> 5][(i1 & 31) * 4];
        p1[0] = f2tf32(rb1.x); p1[1] = f2tf32(rb1.y);
        p1[2] = f2tf32(rb1.z); p1[3] = f2tf32(rb1.w);
    };
    auto compute = [&](int st) {
#pragma unroll
        for (int ks = 0; ks < 2; ks++) {
            const int r0 = ks * 8 + tig, r1 = r0 + 4;
            unsigned afr[2][4], bfr[4][2];
#pragma unroll
            for (int mt = 0; mt < 2; mt++) {
                int m = wm * 32 + mt * 16 + gid;
                afr[mt][0] = sA[st][r0][SWZ(m, r0)];
                afr[mt][1] = sA[st][r0][SWZ(m + 8, r0)];
                afr[mt][2] = sA[st][r1][SWZ(m, r1)];
                afr[mt][3] = sA[st][r1][SWZ(m + 8, r1)];
            }
#pragma unroll
            for (int nt = 0; nt < 4; nt++) {
                int n = wn * 32 + nt * 8 + gid;
                bfr[nt][0] = sB[st][r0][n];
                bfr[nt][1] = sB[st][r1][n];
            }
#pragma unroll
            for (int mt = 0; mt < 2; mt++)
#pragma unroll
                for (int nt = 0; nt < 4; nt++)
                    mma_tf32(acc[mt][nt], afr[mt], bfr[nt]);
        }
    };

    ldg(0); sts(0); __syncthreads();
#pragma unroll 1
    for (int ch = 0; ch < 16; ch++) {
        int st = ch & 1;
        if (ch < 15) ldg((ch + 1) * 16);
        compute(st);
        if (ch < 15) sts(st ^ 1);
        __syncthreads();
    }

#pragma unroll
    for (int mt = 0; mt < 2; mt++) {
        int o = o0 + wm * 32 + mt * 16 + gid;
        float bi0 = bb[o], bi1 = bb[o + 8];
#pragma unroll
        for (int nt = 0; nt < 4; nt++) {
            int n = n0 + wn * 32 + nt * 8 + tig * 2;
            float2 v0 = {acc[mt][nt][0] + bi0, acc[mt][nt][1] + bi0};
            float2 v1 = {acc[mt][nt][2] + bi1, acc[mt][nt][3] + bi1};
            *(float2*)&g_bcdt[(size_t)(b * O3 + o) * NN + n] = v0;
            *(float2*)&g_bcdt[(size_t)(b * O3 + o + 8) * NN + n] = v1;
        }
    }
}

// ============================================================
// K2: depthwise 3x3x3 conv (pad 1) + b_dw
//     tile 4d x 4h x 64w, 4 outputs/thread (halo amortized)
// ============================================================
__global__ __launch_bounds__(256) void k2_dwconv(
    const float* __restrict__ Wdw, const float* __restrict__ bdw)
{
    __shared__ float s_in[6][6][66];
    __shared__ float s_w[27];

    const int z  = blockIdx.z;          // b*192 + ch
    const int ch = z % O3;
    const int d0 = blockIdx.y * 4;
    const int h0 = blockIdx.x * 4;
    const int tid = threadIdx.x;
    const int tx = tid & 63, tq = tid >> 6;   // tq = local h

    const float* in = g_bcdt + (size_t)z * NN;
    if (tid < 27) s_w[tid] = Wdw[ch * 27 + tid];

    for (int idx = tid; idx < 6 * 6 * 66; idx += 256) {
        int dd = idx / 396;
        int r  = idx % 396;
        int hh = r / 66, ww = r % 66;
        int gd = d0 + dd - 1, gh = h0 + hh - 1, gw = ww - 1;
        float v = 0.f;
        if (gd >= 0 && gd < DD && gh >= 0 && gh < HH && gw >= 0 && gw < WW)
            v = in[(size_t)gd * (HH * WW) + gh * WW + gw];
        s_in[dd][hh][ww] = v;
    }
    __syncthreads();

    const float bias = bdw[ch];
    float* outp = g_bcdt2 + (size_t)z * NN;
#pragma unroll
    for (int dd = 0; dd < 4; dd++) {
        float acc = bias;
#pragma unroll
        for (int kd = 0; kd < 3; kd++)
#pragma unroll
            for (int kh = 0; kh < 3; kh++)
#pragma unroll
                for (int kw = 0; kw < 3; kw++)
                    acc += s_w[kd * 9 + kh * 3 + kw] * s_in[dd + kd][tq + kh][tx + kw];
        outp[(size_t)(d0 + dd) * (HH * WW) + (h0 + tq) * WW + tx] = acc;
    }
}

// ============================================================
// K3: AB = softmax_n(dt) * B_   (+A[s] cancels; __expf = MUFU)
// ============================================================
__global__ __launch_bounds__(256) void k3_softmax_ab()
{
    const int bs = blockIdx.x;
    const int b = bs >> 6, s = bs & 63;
    const float4* dt   = (const float4*)(g_bcdt2 + (size_t)(b * O3 + 128 + s) * NN);
    const float4* Brow = (const float4*)(g_bcdt2 + (size_t)(b * O3 + s) * NN);
    float4* ab = (float4*)(g_ab + (size_t)(b * SS + s) * NN);
    const int tid = threadIdx.x;
    __shared__ float red[256];

    float m = -1e30f;
    for (int i = tid; i < NN / 4; i += 256) {
        float4 v = dt[i];
        m = fmaxf(m, fmaxf(fmaxf(v.x, v.y), fmaxf(v.z, v.w)));
    }
    red[tid] = m; __syncthreads();
    for (int off = 128; off > 0; off >>= 1) {
        if (tid < off) red[tid] = fmaxf(red[tid], red[tid + off]);
        __syncthreads();
    }
    m = red[0]; __syncthreads();

    float sum = 0.f;
    for (int i = tid; i < NN / 4; i += 256) {
        float4 v = dt[i];
        sum += __expf(v.x - m) + __expf(v.y - m) + __expf(v.z - m) + __expf(v.w - m);
    }
    red[tid] = sum; __syncthreads();
    for (int off = 128; off > 0; off >>= 1) {
        if (tid < off) red[tid] += red[tid + off];
        __syncthreads();
    }
    const float inv = 1.f / red[0];
    __syncthreads();

    for (int i = tid; i < NN / 4; i += 256) {
        float4 v = dt[i];
        float4 bv = Brow[i];
        float4 o;
        o.x = __expf(v.x - m) * inv * bv.x;
        o.y = __expf(v.y - m) * inv * bv.y;
        o.z = __expf(v.z - m) * inv * bv.z;
        o.w = __expf(v.w - m) * inv * bv.w;
        ab[i] = o;
    }
}

// ============================================================
// T4: split-K partials of h[b,c,s] = sum_n x[b,c,n]*AB[b,s,n]
// ============================================================
__global__ __launch_bounds__(256) void t4_h_partial(const float* __restrict__ x)
{
    __shared__ unsigned sA[2][16][136];  // [stage][k][c], swizzled
    __shared__ unsigned sB[2][16][72];   // [stage][k][s], swizzled

    const int split = blockIdx.x;
    const int cbase = blockIdx.y * 128;
    const int b     = blockIdx.z;
    const int nbase = split * NCHUNK;
    const int tid  = threadIdx.x;
    const int warp = tid >> 5, lane = tid & 31;
    const int wm = warp >> 1, wn = warp & 1;     // 4 x 2 warp grid
    const int gid = lane >> 2, tig = lane & 3;

    const float* xb  = x + (size_t)b * CC * NN;
    const float* abb = g_ab + (size_t)b * SS * NN;

    float acc[2][4][4];
#pragma unroll
    for (int i = 0; i < 2; i++)
#pragma unroll
        for (int j = 0; j < 4; j++)
#pragma unroll
            for (int k = 0; k < 4; k++) acc[i][j][k] = 0.f;

    const int ac0 = tid >> 2, akq = tid & 3;
    const int colA = ac0 ^ (akq << 3);
    const int colB = ac0 ^ (akq << 3);   // same mapping for sB (bs_ = ac0)
    float4 ra0, ra1, rb;

    auto ldg = [&](int k0) {
        ra0 = *(const float4*)&xb[(size_t)(cbase + ac0) * NN + nbase + k0 + akq * 4];
        ra1 = *(const float4*)&xb[(size_t)(cbase + 64 + ac0) * NN + nbase + k0 + akq * 4];
        rb  = *(const float4*)&abb[(size_t)ac0 * NN + nbase + k0 + akq * 4];
    };
    auto sts = [&](int st) {
        sA[st][akq * 4 + 0][colA] = f2tf32(ra0.x);
        sA[st][akq * 4 + 1][colA] = f2tf32(ra0.y);
        sA[st][akq * 4 + 2][colA] = f2tf32(ra0.z);
        sA[st][akq * 4 + 3][colA] = f2tf32(ra0.w);
        sA[st][akq * 4 + 0][64 + colA] = f2tf32(ra1.x);
        sA[st][akq * 4 + 1][64 + colA] = f2tf32(ra1.y);
        sA[st][akq * 4 + 2][64 + colA] = f2tf32(ra1.z);
        sA[st][akq * 4 + 3][64 + colA] = f2tf32(ra1.w);
        sB[st][akq * 4 + 0][colB] = f2tf32(rb.x);
        sB[st][akq * 4 + 1][colB] = f2tf32(rb.y);
        sB[st][akq * 4 + 2][colB] = f2tf32(rb.z);
        sB[st][akq * 4 + 3][colB] = f2tf32(rb.w);
    };
    auto compute = [&](int st) {
#pragma unroll
        for (int ks = 0; ks < 2; ks++) {
            const int r0 = ks * 8 + tig, r1 = r0 + 4;
            unsigned afr[2][4], bfr[4][2];
#pragma unroll
            for (int mt = 0; mt < 2; mt++) {
                int m = wm * 32 + mt * 16 + gid;
                afr[mt][0] = sA[st][r0][SWZ(m, r0)];
                afr[mt][1] = sA[st][r0][SWZ(m + 8, r0)];
                afr[mt][2] = sA[st][r1][SWZ(m, r1)];
                afr[mt][3] = sA[st][r1][SWZ(m + 8, r1)];
            }
#pragma unroll
            for (int nt = 0; nt < 4; nt++) {
                int n = wn * 32 + nt * 8 + gid;
                bfr[nt][0] = sB[st][r0][SWZ(n, r0)];
                bfr[nt][1] = sB[st][r1][SWZ(n, r1)];
            }
#pragma unroll
            for (int mt = 0; mt < 2; mt++)
#pragma unroll
                for (int nt = 0; nt < 4; nt++)
                    mma_tf32(acc[mt][nt], afr[mt], bfr[nt]);
        }
    };

    ldg(0); sts(0); __syncthreads();
    const int NCH = NCHUNK / 16;
#pragma unroll 1
    for (int ch = 0; ch < NCH; ch++) {
        int st = ch & 1;
        if (ch < NCH - 1) ldg((ch + 1) * 16);
        compute(st);
        if (ch < NCH - 1) sts(st ^ 1);
        __syncthreads();
    }

    float* dst = g_hpart + (size_t)split * (BB * CC * SS);
#pragma unroll
    for (int mt = 0; mt < 2; mt++) {
        int c = cbase + wm * 32 + mt * 16 + gid;
#pragma unroll
        for (int nt = 0; nt < 4; nt++) {
            int s = wn * 32 + nt * 8 + tig * 2;
            float2 v0 = {acc[mt][nt][0], acc[mt][nt][1]};
            float2 v1 = {acc[mt][nt][2], acc[mt][nt][3]};
            *(float2*)&dst[(size_t)(b * CC + c) * SS + s] = v0;
            *(float2*)&dst[(size_t)(b * CC + c + 8) * SS + s] = v1;
        }
    }
}

// ============================================================
// K5: reduce partials -> h; MLP chain -> h4
// ============================================================
__global__ __launch_bounds__(256) void k5_small(
    const float* __restrict__ Whz, const float* __restrict__ bhz,
    const float* __restrict__ Wout, const float* __restrict__ bout,
    const float* __restrict__ Dp, float* __restrict__ outh4)
{
    const int bs = blockIdx.x;
    const int b = bs >> 6, s = bs & 63;
    const int tid = threadIdx.x;
    __shared__ float sh[256];
    __shared__ float sh3[256];

    float a = 0.f;
    for (int k = 0; k < NSPLIT; k++)
        a += g_hpart[(size_t)k * BB * CC * SS + (size_t)(b * CC + tid) * SS + s];
    sh[tid] = a;
    __syncthreads();

    float a0 = bhz[tid];
    float a1 = bhz[256 + tid];
    for (int c = 0; c < 256; c++) {
        float hv = sh[c];
        a0 += Whz[tid * 256 + c] * hv;
        a1 += Whz[(256 + tid) * 256 + c] * hv;
    }
    float sig = 1.f / (1.f + expf(-a1));
    sh3[tid] = a0 * (a1 * sig + Dp[0]);
    __syncthreads();

    float a2 = bout[tid];
    for (int c = 0; c < 256; c++) a2 += Wout[tid * 256 + c] * sh3[c];

    size_t oi = (size_t)(b * CC + tid) * SS + s;
    g_h4[oi] = a2;
    outh4[oi] = a2;
}

// ============================================================
// T6: y = h4(256x64) @ C_(64x65536)   (tf32 MMA)
// ============================================================
__global__ __launch_bounds__(256) void t6_y(float* __restrict__ y)
{
    __shared__ unsigned sA[2][16][72];   // [stage][k][o], swizzled
    __shared__ unsigned sB[2][16][136];  // [stage][k][n]

    const int b  = blockIdx.z;
    const int o0 = blockIdx.y * 64;
    const int n0 = blockIdx.x * 128;
    const int tid  = threadIdx.x;
    const int warp = tid >> 5, lane = tid & 31;
    const int wm = warp >> 2, wn = warp & 3;
    const int gid = lane >> 2, tig = lane & 3;

    const float* Cb  = g_bcdt2 + (size_t)(b * O3 + 64) * NN;
    const float* h4b = g_h4 + (size_t)b * CC * SS;

    float acc[2][4][4];
#pragma unroll
    for (int i = 0; i < 2; i++)
#pragma unroll
        for (int j = 0; j < 4; j++)
#pragma unroll
            for (int k = 0; k < 4; k++) acc[i][j][k] = 0.f;

    const int ao = tid >> 2, akq = tid & 3;
    const int colA = ao ^ (akq << 3);
    float4 ra, rb0, rb1;

    auto ldg = [&](int s0) {
        ra  = *(const float4*)&h4b[(o0 + ao) * SS + s0 + akq * 4];
        rb0 = *(const float4*)&Cb[(size_t)(s0 + (tid >> 5)) * NN + n0 + (tid & 31) * 4];
        int i1 = tid + 256;
        rb1 = *(const float4*)&Cb[(size_t)(s0 + (i1 >> 5)) * NN + n0 + (i1 & 31) * 4];
    };
    auto sts = [&](int st) {
        sA[st][akq * 4 + 0][colA] = f2tf32(ra.x);
        sA[st][akq * 4 + 1][colA] = f2tf32(ra.y);
        sA[st][akq * 4 + 2][colA] = f2tf32(ra.z);
        sA[st][akq * 4 + 3][colA] = f2tf32(ra.w);
        unsigned* p0 = &sB[st][tid >> 5][(tid & 31) * 4];
        p0[0] = f2tf32(rb0.x); p0[1] = f2tf32(rb0.y);
        p0[2] = f2tf32(rb0.z); p0[3] = f2tf32(rb0.w);
        int i1 = tid + 256;
        unsigned* p1 = &sB[st][i1 >> 5][(i1 & 31) * 4];
        p1[0] = f2tf32(rb1.x); p1[1] = f2tf32(rb1.y);
        p1[2] = f2tf32(rb1.z); p1[3] = f2tf32(rb1.w);
    };
    auto compute = [&](int st) {
#pragma unroll
        for (int ks = 0; ks < 2; ks++) {
            const int r0 = ks * 8 + tig, r1 = r0 + 4;
            unsigned afr[2][4], bfr[4][2];
#pragma unroll
            for (int mt = 0; mt < 2; mt++) {
                int m = wm * 32 + mt * 16 + gid;
                afr[mt][0] = sA[st][r0][SWZ(m, r0)];
                afr[mt][1] = sA[st][r0][SWZ(m + 8, r0)];
                afr[mt][2] = sA[st][r1][SWZ(m, r1)];
                afr[mt][3] = sA[st][r1][SWZ(m + 8, r1)];
            }
#pragma unroll
            for (int nt = 0; nt < 4; nt++) {
                int n = wn * 32 + nt * 8 + gid;
                bfr[nt][0] = sB[st][r0][n];
                bfr[nt][1] = sB[st][r1][n];
            }
#pragma unroll
            for (int mt = 0; mt < 2; mt++)
#pragma unroll
                for (int nt = 0; nt < 4; nt++)
                    mma_tf32(acc[mt][nt], afr[mt], bfr[nt]);
        }
    };

    ldg(0); sts(0); __syncthreads();
#pragma unroll 1
    for (int ch = 0; ch < 4; ch++) {
        int st = ch & 1;
        if (ch < 3) ldg((ch + 1) * 16);
        compute(st);
        if (ch < 3) sts(st ^ 1);
        __syncthreads();
    }

#pragma unroll
    for (int mt = 0; mt < 2; mt++) {
        int o = o0 + wm * 32 + mt * 16 + gid;
#pragma unroll
        for (int nt = 0; nt < 4; nt++) {
            int n = n0 + wn * 32 + nt * 8 + tig * 2;
            float2 v0 = {acc[mt][nt][0], acc[mt][nt][1]};
            float2 v1 = {acc[mt][nt][2], acc[mt][nt][3]};
            *(float2*)&y[(size_t)(b * CC + o) * NN + n] = v0;
            *(float2*)&y[(size_t)(b * CC + o + 8) * NN + n] = v1;
        }
    }
}

// ============================================================
extern "C" void kernel_launch(void* const* d_in, const int* in_sizes, int n_in,
                              void* d_out, int out_size)
{
    const float* x      = (const float*)d_in[0];
    const float* W_bcdt = (const float*)d_in[1];
    const float* b_bcdt = (const float*)d_in[2];
    const float* W_dw   = (const float*)d_in[3];
    const float* b_dw   = (const float*)d_in[4];
    const float* W_hz   = (const float*)d_in[5];
    const float* b_hz   = (const float*)d_in[6];
    const float* W_out  = (const float*)d_in[7];
    const float* b_out  = (const float*)d_in[8];
    // d_in[9] = A : softmax shift-invariant, cancels exactly
    const float* Dp     = (const float*)d_in[10];
    float* out = (float*)d_out;
    float* out_h4 = out + (size_t)BB * CC * NN;   // y (B,C,D,H,W) then h4 (B,C,S)

    t1_bcdt      <<<dim3(NN / 128, O3 / 64, BB), 256>>>(x, W_bcdt, b_bcdt);
    k2_dwconv    <<<dim3(HH / 4, DD / 4, BB * O3), 256>>>(W_dw, b_dw);
    k3_softmax_ab<<<BB * SS, 256>>>();
    t4_h_partial <<<dim3(NSPLIT, CC / 128, BB), 256>>>(x);
    k5_small     <<<BB * SS, 256>>>(W_hz, b_hz, W_out, b_out, Dp, out_h4);
    t6_y         <<<dim3(NN / 128, CC / 64, BB), 256>>>(out);
}

// round 9
// speedup vs baseline: 2.1117x; 1.0361x over previous
#include <cuda_runtime.h>

#define BB 4
#define CC 256
#define SS 64
#define O3 192
#define DD 16
#define HH 64
#define WW 64
#define NN 65536
#define NSPLIT 64
#define NCHUNK (NN / NSPLIT)   // 1024

// ---- scratch (device globals; no cudaMalloc allowed) ----
__device__ float g_bcdt [(size_t)BB * O3 * NN];   // pre-conv  BCdt
__device__ float g_bcdt2[(size_t)BB * O3 * NN];   // post-conv BCdt
__device__ float g_inv  [BB * SS];                // 1 / sum_n exp(dt)
__device__ float g_hpart[(size_t)NSPLIT * BB * CC * SS];
__device__ float g_h4   [(size_t)BB * CC * SS];

// ---- tf32 helpers ----
__device__ __forceinline__ unsigned f2tf32(float f) {
    unsigned r;
    asm("cvt.rna.tf32.f32 %0, %1;" : "=r"(r) : "f"(f));
    return r;
}
__device__ __forceinline__ void mma_tf32(float c[4], const unsigned a[4], const unsigned b[2]) {
    asm volatile(
        "mma.sync.aligned.m16n8k8.row.col.f32.tf32.tf32.f32 "
        "{%0,%1,%2,%3}, {%4,%5,%6,%7}, {%8,%9}, {%0,%1,%2,%3};"
        : "+f"(c[0]), "+f"(c[1]), "+f"(c[2]), "+f"(c[3])
        : "r"(a[0]), "r"(a[1]), "r"(a[2]), "r"(a[3]), "r"(b[0]), "r"(b[1]));
}
// physical-column swizzle for k-major staging (kills 4-way STS conflicts;
// per-instruction-uniform on the LDS side so fragment loads stay clean)
#define SWZ(col, k) ((col) ^ ((((k) >> 2) & 3) << 3))

// ============================================================
// T1: BCdt = W_bcdt(192x256) @ x(256x65536) + bias   (tf32 MMA)
//     grid.x = o-tiles (fastest) so the 3 o-blocks sharing an
//     x n-slice run in the same wave -> L2-hot re-reads
// ============================================================
__global__ __launch_bounds__(256) void t1_bcdt(
    const float* __restrict__ x, const float* __restrict__ Wb,
    const float* __restrict__ bb)
{
    __shared__ unsigned sA[2][16][72];   // [stage][k][o], swizzled cols
    __shared__ unsigned sB[2][16][136];  // [stage][k][n]

    const int b  = blockIdx.z;
    const int o0 = blockIdx.x * 64;
    const int n0 = blockIdx.y * 128;
    const int tid  = threadIdx.x;
    const int warp = tid >> 5, lane = tid & 31;
    const int wm = warp >> 2, wn = warp & 3;     // 2 x 4 warp grid
    const int gid = lane >> 2, tig = lane & 3;

    const float* xb = x + (size_t)b * CC * NN;

    float acc[2][4][4];
#pragma unroll
    for (int i = 0; i < 2; i++)
#pragma unroll
        for (int j = 0; j < 4; j++)
#pragma unroll
            for (int k = 0; k < 4; k++) acc[i][j][k] = 0.f;

    const int ao = tid >> 2, akq = tid & 3;
    const int colA = ao ^ (akq << 3);
    float4 ra, rb0, rb1;

    auto ldg = [&](int c0) {
        ra  = *(const float4*)&Wb[(o0 + ao) * CC + c0 + akq * 4];
        rb0 = *(const float4*)&xb[(size_t)(c0 + (tid >> 5)) * NN + n0 + (tid & 31) * 4];
        int i1 = tid + 256;
        rb1 = *(const float4*)&xb[(size_t)(c0 + (i1 >> 5)) * NN + n0 + (i1 & 31) * 4];
    };
    auto sts = [&](int st) {
        sA[st][akq * 4 + 0][colA] = f2tf32(ra.x);
        sA[st][akq * 4 + 1][colA] = f2tf32(ra.y);
        sA[st][akq * 4 + 2][colA] = f2tf32(ra.z);
        sA[st][akq * 4 + 3][colA] = f2tf32(ra.w);
        unsigned* p0 = &sB[st][tid >> 5][(tid & 31) * 4];
        p0[0] = f2tf32(rb0.x); p0[1] = f2tf32(rb0.y);
        p0[2] = f2tf32(rb0.z); p0[3] = f2tf32(rb0.w);
        int i1 = tid + 256;
        unsigned* p1 = &sB[st][i1 >> 5][(i1 & 31) * 4];
        p1[0] = f2tf32(rb1.x); p1[1] = f2tf32(rb1.y);
        p1[2] = f2tf32(rb1.z); p1[3] = f2tf32(rb1.w);
    };
    auto compute = [&](int st) {
#pragma unroll
        for (int ks = 0; ks < 2; ks++) {
            const int r0 = ks * 8 + tig, r1 = r0 + 4;
            unsigned afr[2][4], bfr[4][2];
#pragma unroll
            for (int mt = 0; mt < 2; mt++) {
                int m = wm * 32 + mt * 16 + gid;
                afr[mt][0] = sA[st][r0][SWZ(m, r0)];
                afr[mt][1] = sA[st][r0][SWZ(m + 8, r0)];
                afr[mt][2] = sA[st][r1][SWZ(m, r1)];
                afr[mt][3] = sA[st][r1][SWZ(m + 8, r1)];
            }
#pragma unroll
            for (int nt = 0; nt < 4; nt++) {
                int n = wn * 32 + nt * 8 + gid;
                bfr[nt][0] = sB[st][r0][n];
                bfr[nt][1] = sB[st][r1][n];
            }
#pragma unroll
            for (int mt = 0; mt < 2; mt++)
#pragma unroll
                for (int nt = 0; nt < 4; nt++)
                    mma_tf32(acc[mt][nt], afr[mt], bfr[nt]);
        }
    };

    ldg(0); sts(0); __syncthreads();
#pragma unroll 1
    for (int ch = 0; ch < 16; ch++) {
        int st = ch & 1;
        if (ch < 15) ldg((ch + 1) * 16);
        compute(st);
        if (ch < 15) sts(st ^ 1);
        __syncthreads();
    }

#pragma unroll
    for (int mt = 0; mt < 2; mt++) {
        int o = o0 + wm * 32 + mt * 16 + gid;
        float bi0 = bb[o], bi1 = bb[o + 8];
#pragma unroll
        for (int nt = 0; nt < 4; nt++) {
            int n = n0 + wn * 32 + nt * 8 + tig * 2;
            float2 v0 = {acc[mt][nt][0] + bi0, acc[mt][nt][1] + bi0};
            float2 v1 = {acc[mt][nt][2] + bi1, acc[mt][nt][3] + bi1};
            *(float2*)&g_bcdt[(size_t)(b * O3 + o) * NN + n] = v0;
            *(float2*)&g_bcdt[(size_t)(b * O3 + o + 8) * NN + n] = v1;
        }
    }
}

// ============================================================
// K2: depthwise 3x3x3 conv (pad 1) + b_dw
//     tile 4d x 4h x 64w, 4 outputs/thread
// ============================================================
__global__ __launch_bounds__(256) void k2_dwconv(
    const float* __restrict__ Wdw, const float* __restrict__ bdw)
{
    __shared__ float s_in[6][6][66];
    __shared__ float s_w[27];

    const int z  = blockIdx.z;          // b*192 + ch
    const int ch = z % O3;
    const int d0 = blockIdx.y * 4;
    const int h0 = blockIdx.x * 4;
    const int tid = threadIdx.x;
    const int tx = tid & 63, tq = tid >> 6;

    const float* in = g_bcdt + (size_t)z * NN;
    if (tid < 27) s_w[tid] = Wdw[ch * 27 + tid];

    for (int idx = tid; idx < 6 * 6 * 66; idx += 256) {
        int dd = idx / 396;
        int r  = idx % 396;
        int hh = r / 66, ww = r % 66;
        int gd = d0 + dd - 1, gh = h0 + hh - 1, gw = ww - 1;
        float v = 0.f;
        if (gd >= 0 && gd < DD && gh >= 0 && gh < HH && gw >= 0 && gw < WW)
            v = in[(size_t)gd * (HH * WW) + gh * WW + gw];
        s_in[dd][hh][ww] = v;
    }
    __syncthreads();

    const float bias = bdw[ch];
    float* outp = g_bcdt2 + (size_t)z * NN;
#pragma unroll
    for (int dd = 0; dd < 4; dd++) {
        float acc = bias;
#pragma unroll
        for (int kd = 0; kd < 3; kd++)
#pragma unroll
            for (int kh = 0; kh < 3; kh++)
#pragma unroll
                for (int kw = 0; kw < 3; kw++)
                    acc += s_w[kd * 9 + kh * 3 + kw] * s_in[dd + kd][tq + kh][tx + kw];
        outp[(size_t)(d0 + dd) * (HH * WW) + (h0 + tq) * WW + tx] = acc;
    }
}

// ============================================================
// K3: g_inv[b,s] = 1 / sum_n exp(dt[b,s,n])
//     single pass; +A[s] cancels, max-shift cancels (range safe)
// ============================================================
__global__ __launch_bounds__(256) void k3_expsum()
{
    const int bs = blockIdx.x;
    const int b = bs >> 6, s = bs & 63;
    const float4* dt = (const float4*)(g_bcdt2 + (size_t)(b * O3 + 128 + s) * NN);
    const int tid = threadIdx.x;
    __shared__ float red[256];

    float sum = 0.f;
    for (int i = tid; i < NN / 4; i += 256) {
        float4 v = dt[i];
        sum += __expf(v.x) + __expf(v.y) + __expf(v.z) + __expf(v.w);
    }
    red[tid] = sum; __syncthreads();
    for (int off = 128; off > 0; off >>= 1) {
        if (tid < off) red[tid] += red[tid + off];
        __syncthreads();
    }
    if (tid == 0) g_inv[bs] = 1.f / red[0];
}

// ============================================================
// T4: split-K partials of G[b,c,s] = sum_n x[b,c,n] * exp(dt[b,s,n]) * B_[b,s,n]
//     (softmax 1/denominator factored out; applied in K5)
// ============================================================
__global__ __launch_bounds__(256) void t4_h_partial(const float* __restrict__ x)
{
    __shared__ unsigned sA[2][16][136];  // [stage][k][c], swizzled
    __shared__ unsigned sB[2][16][72];   // [stage][k][s], swizzled

    const int split = blockIdx.x;
    const int cbase = blockIdx.y * 128;
    const int b     = blockIdx.z;
    const int nbase = split * NCHUNK;
    const int tid  = threadIdx.x;
    const int warp = tid >> 5, lane = tid & 31;
    const int wm = warp >> 1, wn = warp & 1;     // 4 x 2 warp grid
    const int gid = lane >> 2, tig = lane & 3;

    const float* xb  = x + (size_t)b * CC * NN;
    const float* dtb = g_bcdt2 + (size_t)(b * O3 + 128) * NN;  // dt rows
    const float* bvb = g_bcdt2 + (size_t)(b * O3) * NN;        // B_ rows

    float acc[2][4][4];
#pragma unroll
    for (int i = 0; i < 2; i++)
#pragma unroll
        for (int j = 0; j < 4; j++)
#pragma unroll
            for (int k = 0; k < 4; k++) acc[i][j][k] = 0.f;

    const int ac0 = tid >> 2, akq = tid & 3;
    const int colA = ac0 ^ (akq << 3);
    float4 ra0, ra1, rdt, rbv;

    auto ldg = [&](int k0) {
        ra0 = *(const float4*)&xb[(size_t)(cbase + ac0) * NN + nbase + k0 + akq * 4];
        ra1 = *(const float4*)&xb[(size_t)(cbase + 64 + ac0) * NN + nbase + k0 + akq * 4];
        rdt = *(const float4*)&dtb[(size_t)ac0 * NN + nbase + k0 + akq * 4];
        rbv = *(const float4*)&bvb[(size_t)ac0 * NN + nbase + k0 + akq * 4];
    };
    auto sts = [&](int st) {
        sA[st][akq * 4 + 0][colA] = f2tf32(ra0.x);
        sA[st][akq * 4 + 1][colA] = f2tf32(ra0.y);
        sA[st][akq * 4 + 2][colA] = f2tf32(ra0.z);
        sA[st][akq * 4 + 3][colA] = f2tf32(ra0.w);
        sA[st][akq * 4 + 0][64 + colA] = f2tf32(ra1.x);
        sA[st][akq * 4 + 1][64 + colA] = f2tf32(ra1.y);
        sA[st][akq * 4 + 2][64 + colA] = f2tf32(ra1.z);
        sA[st][akq * 4 + 3][64 + colA] = f2tf32(ra1.w);
        sB[st][akq * 4 + 0][colA] = f2tf32(__expf(rdt.x) * rbv.x);
        sB[st][akq * 4 + 1][colA] = f2tf32(__expf(rdt.y) * rbv.y);
        sB[st][akq * 4 + 2][colA] = f2tf32(__expf(rdt.z) * rbv.z);
        sB[st][akq * 4 + 3][colA] = f2tf32(__expf(rdt.w) * rbv.w);
    };
    auto compute = [&](int st) {
#pragma unroll
        for (int ks = 0; ks < 2; ks++) {
            const int r0 = ks * 8 + tig, r1 = r0 + 4;
            unsigned afr[2][4], bfr[4][2];
#pragma unroll
            for (int mt = 0; mt < 2; mt++) {
                int m = wm * 32 + mt * 16 + gid;
                afr[mt][0] = sA[st][r0][SWZ(m, r0)];
                afr[mt][1] = sA[st][r0][SWZ(m + 8, r0)];
                afr[mt][2] = sA[st][r1][SWZ(m, r1)];
                afr[mt][3] = sA[st][r1][SWZ(m + 8, r1)];
            }
#pragma unroll
            for (int nt = 0; nt < 4; nt++) {
                int n = wn * 32 + nt * 8 + gid;
                bfr[nt][0] = sB[st][r0][SWZ(n, r0)];
                bfr[nt][1] = sB[st][r1][SWZ(n, r1)];
            }
#pragma unroll
            for (int mt = 0; mt < 2; mt++)
#pragma unroll
                for (int nt = 0; nt < 4; nt++)
                    mma_tf32(acc[mt][nt], afr[mt], bfr[nt]);
        }
    };

    ldg(0); sts(0); __syncthreads();
    const int NCH = NCHUNK / 16;
#pragma unroll 1
    for (int ch = 0; ch < NCH; ch++) {
        int st = ch & 1;
        if (ch < NCH - 1) ldg((ch + 1) * 16);
        compute(st);
        if (ch < NCH - 1) sts(st ^ 1);
        __syncthreads();
    }

    float* dst = g_hpart + (size_t)split * (BB * CC * SS);
#pragma unroll
    for (int mt = 0; mt < 2; mt++) {
        int c = cbase + wm * 32 + mt * 16 + gid;
#pragma unroll
        for (int nt = 0; nt < 4; nt++) {
            int s = wn * 32 + nt * 8 + tig * 2;
            float2 v0 = {acc[mt][nt][0], acc[mt][nt][1]};
            float2 v1 = {acc[mt][nt][2], acc[mt][nt][3]};
            *(float2*)&dst[(size_t)(b * CC + c) * SS + s] = v0;
            *(float2*)&dst[(size_t)(b * CC + c + 8) * SS + s] = v1;
        }
    }
}

// ============================================================
// K5: reduce partials, apply softmax 1/denom, MLP chain -> h4
// ============================================================
__global__ __launch_bounds__(256) void k5_small(
    const float* __restrict__ Whz, const float* __restrict__ bhz,
    const float* __restrict__ Wout, const float* __restrict__ bout,
    const float* __restrict__ Dp, float* __restrict__ outh4)
{
    const int bs = blockIdx.x;
    const int b = bs >> 6, s = bs & 63;
    const int tid = threadIdx.x;
    __shared__ float sh[256];
    __shared__ float sh3[256];

    const float inv = g_inv[bs];
    float a = 0.f;
    for (int k = 0; k < NSPLIT; k++)
        a += g_hpart[(size_t)k * BB * CC * SS + (size_t)(b * CC + tid) * SS + s];
    sh[tid] = a * inv;
    __syncthreads();

    float a0 = bhz[tid];
    float a1 = bhz[256 + tid];
    for (int c = 0; c < 256; c++) {
        float hv = sh[c];
        a0 += Whz[tid * 256 + c] * hv;
        a1 += Whz[(256 + tid) * 256 + c] * hv;
    }
    float sig = 1.f / (1.f + expf(-a1));
    sh3[tid] = a0 * (a1 * sig + Dp[0]);
    __syncthreads();

    float a2 = bout[tid];
    for (int c = 0; c < 256; c++) a2 += Wout[tid * 256 + c] * sh3[c];

    size_t oi = (size_t)(b * CC + tid) * SS + s;
    g_h4[oi] = a2;
    outh4[oi] = a2;
}

// ============================================================
// T6: y = h4(256x64) @ C_(64x65536)   (tf32 MMA)
//     grid.x = o-tiles (fastest) for L2-hot C_ re-reads
// ============================================================
__global__ __launch_bounds__(256) void t6_y(float* __restrict__ y)
{
    __shared__ unsigned sA[2][16][72];   // [stage][k][o], swizzled
    __shared__ unsigned sB[2][16][136];  // [stage][k][n]

    const int b  = blockIdx.z;
    const int o0 = blockIdx.x * 64;
    const int n0 = blockIdx.y * 128;
    const int tid  = threadIdx.x;
    const int warp = tid >> 5, lane = tid & 31;
    const int wm = warp >> 2, wn = warp & 3;
    const int gid = lane >> 2, tig = lane & 3;

    const float* Cb  = g_bcdt2 + (size_t)(b * O3 + 64) * NN;
    const float* h4b = g_h4 + (size_t)b * CC * SS;

    float acc[2][4][4];
#pragma unroll
    for (int i = 0; i < 2; i++)
#pragma unroll
        for (int j = 0; j < 4; j++)
#pragma unroll
            for (int k = 0; k < 4; k++) acc[i][j][k] = 0.f;

    const int ao = tid >> 2, akq = tid & 3;
    const int colA = ao ^ (akq << 3);
    float4 ra, rb0, rb1;

    auto ldg = [&](int s0) {
        ra  = *(const float4*)&h4b[(o0 + ao) * SS + s0 + akq * 4];
        rb0 = *(const float4*)&Cb[(size_t)(s0 + (tid >> 5)) * NN + n0 + (tid & 31) * 4];
        int i1 = tid + 256;
        rb1 = *(const float4*)&Cb[(size_t)(s0 + (i1 >> 5)) * NN + n0 + (i1 & 31) * 4];
    };
    auto sts = [&](int st) {
        sA[st][akq * 4 + 0][colA] = f2tf32(ra.x);
        sA[st][akq * 4 + 1][colA] = f2tf32(ra.y);
        sA[st][akq * 4 + 2][colA] = f2tf32(ra.z);
        sA[st][akq * 4 + 3][colA] = f2tf32(ra.w);
        unsigned* p0 = &sB[st][tid >> 5][(tid & 31) * 4];
        p0[0] = f2tf32(rb0.x); p0[1] = f2tf32(rb0.y);
        p0[2] = f2tf32(rb0.z); p0[3] = f2tf32(rb0.w);
        int i1 = tid + 256;
        unsigned* p1 = &sB[st][i1 >> 5][(i1 & 31) * 4];
        p1[0] = f2tf32(rb1.x); p1[1] = f2tf32(rb1.y);
        p1[2] = f2tf32(rb1.z); p1[3] = f2tf32(rb1.w);
    };
    auto compute = [&](int st) {
#pragma unroll
        for (int ks = 0; ks < 2; ks++) {
            const int r0 = ks * 8 + tig, r1 = r0 + 4;
            unsigned afr[2][4], bfr[4][2];
#pragma unroll
            for (int mt = 0; mt < 2; mt++) {
                int m = wm * 32 + mt * 16 + gid;
                afr[mt][0] = sA[st][r0][SWZ(m, r0)];
                afr[mt][1] = sA[st][r0][SWZ(m + 8, r0)];
                afr[mt][2] = sA[st][r1][SWZ(m, r1)];
                afr[mt][3] = sA[st][r1][SWZ(m + 8, r1)];
            }
#pragma unroll
            for (int nt = 0; nt < 4; nt++) {
                int n = wn * 32 + nt * 8 + gid;
                bfr[nt][0] = sB[st][r0][n];
                bfr[nt][1] = sB[st][r1][n];
            }
#pragma unroll
            for (int mt = 0; mt < 2; mt++)
#pragma unroll
                for (int nt = 0; nt < 4; nt++)
                    mma_tf32(acc[mt][nt], afr[mt], bfr[nt]);
        }
    };

    ldg(0); sts(0); __syncthreads();
#pragma unroll 1
    for (int ch = 0; ch < 4; ch++) {
        int st = ch & 1;
        if (ch < 3) ldg((ch + 1) * 16);
        compute(st);
        if (ch < 3) sts(st ^ 1);
        __syncthreads();
    }

#pragma unroll
    for (int mt = 0; mt < 2; mt++) {
        int o = o0 + wm * 32 + mt * 16 + gid;
#pragma unroll
        for (int nt = 0; nt < 4; nt++) {
            int n = n0 + wn * 32 + nt * 8 + tig * 2;
            float2 v0 = {acc[mt][nt][0], acc[mt][nt][1]};
            float2 v1 = {acc[mt][nt][2], acc[mt][nt][3]};
            *(float2*)&y[(size_t)(b * CC + o) * NN + n] = v0;
            *(float2*)&y[(size_t)(b * CC + o + 8) * NN + n] = v1;
        }
    }
}

// ============================================================
extern "C" void kernel_launch(void* const* d_in, const int* in_sizes, int n_in,
                              void* d_out, int out_size)
{
    const float* x      = (const float*)d_in[0];
    const float* W_bcdt = (const float*)d_in[1];
    const float* b_bcdt = (const float*)d_in[2];
    const float* W_dw   = (const float*)d_in[3];
    const float* b_dw   = (const float*)d_in[4];
    const float* W_hz   = (const float*)d_in[5];
    const float* b_hz   = (const float*)d_in[6];
    const float* W_out  = (const float*)d_in[7];
    const float* b_out  = (const float*)d_in[8];
    // d_in[9] = A : softmax shift-invariant, cancels exactly
    const float* Dp     = (const float*)d_in[10];
    float* out = (float*)d_out;
    float* out_h4 = out + (size_t)BB * CC * NN;   // y (B,C,D,H,W) then h4 (B,C,S)

    t1_bcdt      <<<dim3(O3 / 64, NN / 128, BB), 256>>>(x, W_bcdt, b_bcdt);
    k2_dwconv    <<<dim3(HH / 4, DD / 4, BB * O3), 256>>>(W_dw, b_dw);
    k3_expsum    <<<BB * SS, 256>>>();
    t4_h_partial <<<dim3(NSPLIT, CC / 128, BB), 256>>>(x);
    k5_small     <<<BB * SS, 256>>>(W_hz, b_hz, W_out, b_out, Dp, out_h4);
    t6_y         <<<dim3(CC / 64, NN / 128, BB), 256>>>(out);
}

// round 10
// speedup vs baseline: 2.2243x; 1.0533x over previous
#include <cuda_runtime.h>

#define BB 4
#define CC 256
#define SS 64
#define O3 192
#define DD 16
#define HH 64
#define WW 64
#define NN 65536
#define NSPLIT 128
#define NCHUNK (NN / NSPLIT)   // 512

// ---- scratch (device globals; no cudaMalloc allowed) ----
__device__ float g_bcdt [(size_t)BB * O3 * NN];   // pre-conv  BCdt
__device__ float g_bcdt2[(size_t)BB * O3 * NN];   // post-conv BCdt
__device__ float g_psum [BB * SS * 64];           // per-block exp partials
__device__ float g_inv  [BB * SS];                // 1 / sum_n exp(dt)
__device__ float g_hpart[(size_t)NSPLIT * BB * CC * SS];
__device__ float g_h4   [(size_t)BB * CC * SS];

// ---- tf32 helpers ----
__device__ __forceinline__ unsigned f2tf32(float f) {
    unsigned r;
    asm("cvt.rna.tf32.f32 %0, %1;" : "=r"(r) : "f"(f));
    return r;
}
__device__ __forceinline__ void mma_tf32(float c[4], const unsigned a[4], const unsigned b[2]) {
    asm volatile(
        "mma.sync.aligned.m16n8k8.row.col.f32.tf32.tf32.f32 "
        "{%0,%1,%2,%3}, {%4,%5,%6,%7}, {%8,%9}, {%0,%1,%2,%3};"
        : "+f"(c[0]), "+f"(c[1]), "+f"(c[2]), "+f"(c[3])
        : "r"(a[0]), "r"(a[1]), "r"(a[2]), "r"(a[3]), "r"(b[0]), "r"(b[1]));
}
// physical-column swizzle for k-major scattered staging (kills 4-way STS
// conflicts; (k>>2) is warp-uniform per LDS instruction so loads stay clean)
#define SWZ(col, k) ((col) ^ ((((k) >> 2) & 3) << 3))

// ============================================================
// T1: BCdt = W_bcdt(192x256) @ x(256x65536) + bias   (tf32 MMA)
//     block tile 64o x 256n, warp tile 64x32 (mt4 x nt4)
// ============================================================
__global__ __launch_bounds__(256, 2) void t1_bcdt(
    const float* __restrict__ x, const float* __restrict__ Wb,
    const float* __restrict__ bb)
{
    __shared__ __align__(16) unsigned sA[2][16][72];   // [k][o], swizzled
    __shared__ __align__(16) unsigned sB[2][16][264];  // [k][n]

    const int b  = blockIdx.z;
    const int o0 = blockIdx.x * 64;
    const int n0 = blockIdx.y * 256;
    const int tid  = threadIdx.x;
    const int wn   = tid >> 5;           // warp 0..7 -> n strip
    const int lane = tid & 31;
    const int gid = lane >> 2, tig = lane & 3;

    const float* xb = x + (size_t)b * CC * NN;

    float acc[4][4][4];
#pragma unroll
    for (int i = 0; i < 4; i++)
#pragma unroll
        for (int j = 0; j < 4; j++)
#pragma unroll
            for (int k = 0; k < 4; k++) acc[i][j][k] = 0.f;

    const int ao = tid >> 2, akq = tid & 3;
    const int colA = ao ^ (akq << 3);
    float4 ra, rb[4];

    auto ldg = [&](int c0) {
        ra = *(const float4*)&Wb[(o0 + ao) * CC + c0 + akq * 4];
#pragma unroll
        for (int t = 0; t < 4; t++) {
            int idx = tid + t * 256;
            rb[t] = *(const float4*)&xb[(size_t)(c0 + (idx >> 6)) * NN + n0 + (idx & 63) * 4];
        }
    };
    auto sts = [&](int st) {
        sA[st][akq * 4 + 0][colA] = f2tf32(ra.x);
        sA[st][akq * 4 + 1][colA] = f2tf32(ra.y);
        sA[st][akq * 4 + 2][colA] = f2tf32(ra.z);
        sA[st][akq * 4 + 3][colA] = f2tf32(ra.w);
#pragma unroll
        for (int t = 0; t < 4; t++) {
            int idx = tid + t * 256;
            uint4 v = {f2tf32(rb[t].x), f2tf32(rb[t].y), f2tf32(rb[t].z), f2tf32(rb[t].w)};
            *(uint4*)&sB[st][idx >> 6][(idx & 63) * 4] = v;
        }
    };
    auto compute = [&](int st) {
#pragma unroll
        for (int ks = 0; ks < 2; ks++) {
            const int r0 = ks * 8 + tig, r1 = r0 + 4;
            unsigned afr[4][4], bfr[4][2];
#pragma unroll
            for (int mt = 0; mt < 4; mt++) {
                int m = mt * 16 + gid;
                afr[mt][0] = sA[st][r0][SWZ(m, r0)];
                afr[mt][1] = sA[st][r0][SWZ(m + 8, r0)];
                afr[mt][2] = sA[st][r1][SWZ(m, r1)];
                afr[mt][3] = sA[st][r1][SWZ(m + 8, r1)];
            }
#pragma unroll
            for (int nt = 0; nt < 4; nt++) {
                int n = wn * 32 + nt * 8 + gid;
                bfr[nt][0] = sB[st][r0][n];
                bfr[nt][1] = sB[st][r1][n];
            }
#pragma unroll
            for (int mt = 0; mt < 4; mt++)
#pragma unroll
                for (int nt = 0; nt < 4; nt++)
                    mma_tf32(acc[mt][nt], afr[mt], bfr[nt]);
        }
    };

    ldg(0); sts(0); __syncthreads();
#pragma unroll 1
    for (int ch = 0; ch < 16; ch++) {
        int st = ch & 1;
        if (ch < 15) ldg((ch + 1) * 16);
        compute(st);
        if (ch < 15) sts(st ^ 1);
        __syncthreads();
    }

#pragma unroll
    for (int mt = 0; mt < 4; mt++) {
        int o = o0 + mt * 16 + gid;
        float bi0 = bb[o], bi1 = bb[o + 8];
#pragma unroll
        for (int nt = 0; nt < 4; nt++) {
            int n = n0 + wn * 32 + nt * 8 + tig * 2;
            float2 v0 = {acc[mt][nt][0] + bi0, acc[mt][nt][1] + bi0};
            float2 v1 = {acc[mt][nt][2] + bi1, acc[mt][nt][3] + bi1};
            *(float2*)&g_bcdt[(size_t)(b * O3 + o) * NN + n] = v0;
            *(float2*)&g_bcdt[(size_t)(b * O3 + o + 8) * NN + n] = v1;
        }
    }
}

// ============================================================
// K2: depthwise 3x3x3 conv (pad 1) + b_dw; for dt channels also
//     emits per-block sum of exp() partials (slot-deterministic)
// ============================================================
__global__ __launch_bounds__(256) void k2_dwconv(
    const float* __restrict__ Wdw, const float* __restrict__ bdw)
{
    __shared__ float s_in[6][6][66];
    __shared__ float s_w[27];
    __shared__ float s_red[256];

    const int z  = blockIdx.z;          // b*192 + ch
    const int ch = z % O3;
    const int b  = z / O3;
    const int d0 = blockIdx.y * 4;
    const int h0 = blockIdx.x * 4;
    const int tid = threadIdx.x;
    const int tx = tid & 63, tq = tid >> 6;

    const float* in = g_bcdt + (size_t)z * NN;
    if (tid < 27) s_w[tid] = Wdw[ch * 27 + tid];

    for (int idx = tid; idx < 6 * 6 * 66; idx += 256) {
        int dd = idx / 396;
        int r  = idx % 396;
        int hh = r / 66, ww = r % 66;
        int gd = d0 + dd - 1, gh = h0 + hh - 1, gw = ww - 1;
        float v = 0.f;
        if (gd >= 0 && gd < DD && gh >= 0 && gh < HH && gw >= 0 && gw < WW)
            v = in[(size_t)gd * (HH * WW) + gh * WW + gw];
        s_in[dd][hh][ww] = v;
    }
    __syncthreads();

    const float bias = bdw[ch];
    float* outp = g_bcdt2 + (size_t)z * NN;
    float esum = 0.f;
#pragma unroll
    for (int dd = 0; dd < 4; dd++) {
        float acc = bias;
#pragma unroll
        for (int kd = 0; kd < 3; kd++)
#pragma unroll
            for (int kh = 0; kh < 3; kh++)
#pragma unroll
                for (int kw = 0; kw < 3; kw++)
                    acc += s_w[kd * 9 + kh * 3 + kw] * s_in[dd + kd][tq + kh][tx + kw];
        outp[(size_t)(d0 + dd) * (HH * WW) + (h0 + tq) * WW + tx] = acc;
        esum += __expf(acc);
    }

    if (ch >= 128) {          // dt channel: block-level exp partial
        s_red[tid] = esum;
        __syncthreads();
        for (int off = 128; off > 0; off >>= 1) {
            if (tid < off) s_red[tid] += s_red[tid + off];
            __syncthreads();
        }
        if (tid == 0) {
            int slot = blockIdx.x + (HH / 4) * blockIdx.y;   // 0..63
            g_psum[(b * SS + (ch - 128)) * 64 + slot] = s_red[0];
        }
    }
}

// ============================================================
// K3: reduce 64 partials -> g_inv   (tiny)
// ============================================================
__global__ void k3_red()
{
    const int bs = blockIdx.x;
    const int t = threadIdx.x;      // 64 threads
    __shared__ float r[64];
    r[t] = g_psum[bs * 64 + t];
    __syncthreads();
    for (int off = 32; off > 0; off >>= 1) {
        if (t < off) r[t] += r[t + off];
        __syncthreads();
    }
    if (t == 0) g_inv[bs] = 1.f / r[0];
}

// ============================================================
// T4: split-K partials of G[b,c,s] = sum_n x[b,c,n]*exp(dt)*B_
//     block tile 256c x 64s, warp tile 64x32 (4x2 warps)
// ============================================================
__global__ __launch_bounds__(256, 2) void t4_h_partial(const float* __restrict__ x)
{
    __shared__ __align__(16) unsigned sA[2][16][264];  // [k][c], swizzled
    __shared__ __align__(16) unsigned sB[2][16][72];   // [k][s], swizzled

    const int split = blockIdx.x;
    const int b     = blockIdx.z;
    const int nbase = split * NCHUNK;
    const int tid  = threadIdx.x;
    const int warp = tid >> 5, lane = tid & 31;
    const int wm = warp >> 1, wn = warp & 1;     // 4 x 2 warp grid
    const int gid = lane >> 2, tig = lane & 3;

    const float* xb  = x + (size_t)b * CC * NN;
    const float* dtb = g_bcdt2 + (size_t)(b * O3 + 128) * NN;
    const float* bvb = g_bcdt2 + (size_t)(b * O3) * NN;

    float acc[4][4][4];
#pragma unroll
    for (int i = 0; i < 4; i++)
#pragma unroll
        for (int j = 0; j < 4; j++)
#pragma unroll
            for (int k = 0; k < 4; k++) acc[i][j][k] = 0.f;

    const int ac0 = tid >> 2, akq = tid & 3;     // ac0 0..63
    const int colA = ac0 ^ (akq << 3);
    float4 ra[4], rdt, rbv;

    auto ldg = [&](int k0) {
#pragma unroll
        for (int j = 0; j < 4; j++)
            ra[j] = *(const float4*)&xb[(size_t)(j * 64 + ac0) * NN + nbase + k0 + akq * 4];
        rdt = *(const float4*)&dtb[(size_t)ac0 * NN + nbase + k0 + akq * 4];
        rbv = *(const float4*)&bvb[(size_t)ac0 * NN + nbase + k0 + akq * 4];
    };
    auto sts = [&](int st) {
#pragma unroll
        for (int j = 0; j < 4; j++) {
            sA[st][akq * 4 + 0][j * 64 + colA] = f2tf32(ra[j].x);
            sA[st][akq * 4 + 1][j * 64 + colA] = f2tf32(ra[j].y);
            sA[st][akq * 4 + 2][j * 64 + colA] = f2tf32(ra[j].z);
            sA[st][akq * 4 + 3][j * 64 + colA] = f2tf32(ra[j].w);
        }
        sB[st][akq * 4 + 0][colA] = f2tf32(__expf(rdt.x) * rbv.x);
        sB[st][akq * 4 + 1][colA] = f2tf32(__expf(rdt.y) * rbv.y);
        sB[st][akq * 4 + 2][colA] = f2tf32(__expf(rdt.z) * rbv.z);
        sB[st][akq * 4 + 3][colA] = f2tf32(__expf(rdt.w) * rbv.w);
    };
    auto compute = [&](int st) {
#pragma unroll
        for (int ks = 0; ks < 2; ks++) {
            const int r0 = ks * 8 + tig, r1 = r0 + 4;
            unsigned afr[4][4], bfr[4][2];
#pragma unroll
            for (int mt = 0; mt < 4; mt++) {
                int m = wm * 64 + mt * 16 + gid;
                afr[mt][0] = sA[st][r0][SWZ(m, r0)];
                afr[mt][1] = sA[st][r0][SWZ(m + 8, r0)];
                afr[mt][2] = sA[st][r1][SWZ(m, r1)];
                afr[mt][3] = sA[st][r1][SWZ(m + 8, r1)];
            }
#pragma unroll
            for (int nt = 0; nt < 4; nt++) {
                int n = wn * 32 + nt * 8 + gid;
                bfr[nt][0] = sB[st][r0][SWZ(n, r0)];
                bfr[nt][1] = sB[st][r1][SWZ(n, r1)];
            }
#pragma unroll
            for (int mt = 0; mt < 4; mt++)
#pragma unroll
                for (int nt = 0; nt < 4; nt++)
                    mma_tf32(acc[mt][nt], afr[mt], bfr[nt]);
        }
    };

    ldg(0); sts(0); __syncthreads();
    const int NCH = NCHUNK / 16;
#pragma unroll 1
    for (int ch = 0; ch < NCH; ch++) {
        int st = ch & 1;
        if (ch < NCH - 1) ldg((ch + 1) * 16);
        compute(st);
        if (ch < NCH - 1) sts(st ^ 1);
        __syncthreads();
    }

    float* dst = g_hpart + (size_t)split * (BB * CC * SS);
#pragma unroll
    for (int mt = 0; mt < 4; mt++) {
        int c = wm * 64 + mt * 16 + gid;
#pragma unroll
        for (int nt = 0; nt < 4; nt++) {
            int s = wn * 32 + nt * 8 + tig * 2;
            float2 v0 = {acc[mt][nt][0], acc[mt][nt][1]};
            float2 v1 = {acc[mt][nt][2], acc[mt][nt][3]};
            *(float2*)&dst[(size_t)(b * CC + c) * SS + s] = v0;
            *(float2*)&dst[(size_t)(b * CC + c + 8) * SS + s] = v1;
        }
    }
}

// ============================================================
// K5: reduce partials, apply softmax 1/denom, MLP chain -> h4
// ============================================================
__global__ __launch_bounds__(256) void k5_small(
    const float* __restrict__ Whz, const float* __restrict__ bhz,
    const float* __restrict__ Wout, const float* __restrict__ bout,
    const float* __restrict__ Dp, float* __restrict__ outh4)
{
    const int bs = blockIdx.x;
    const int b = bs >> 6, s = bs & 63;
    const int tid = threadIdx.x;
    __shared__ float sh[256];
    __shared__ float sh3[256];

    const float inv = g_inv[bs];
    float a = 0.f;
    for (int k = 0; k < NSPLIT; k++)
        a += g_hpart[(size_t)k * BB * CC * SS + (size_t)(b * CC + tid) * SS + s];
    sh[tid] = a * inv;
    __syncthreads();

    float a0 = bhz[tid];
    float a1 = bhz[256 + tid];
    for (int c = 0; c < 256; c++) {
        float hv = sh[c];
        a0 += Whz[tid * 256 + c] * hv;
        a1 += Whz[(256 + tid) * 256 + c] * hv;
    }
    float sig = 1.f / (1.f + expf(-a1));
    sh3[tid] = a0 * (a1 * sig + Dp[0]);
    __syncthreads();

    float a2 = bout[tid];
    for (int c = 0; c < 256; c++) a2 += Wout[tid * 256 + c] * sh3[c];

    size_t oi = (size_t)(b * CC + tid) * SS + s;
    g_h4[oi] = a2;
    outh4[oi] = a2;
}

// ============================================================
// T6: y = h4(256x64) @ C_(64x65536)   (tf32 MMA)
//     block tile 64o x 256n, warp tile 64x32
// ============================================================
__global__ __launch_bounds__(256, 2) void t6_y(float* __restrict__ y)
{
    __shared__ __align__(16) unsigned sA[2][16][72];
    __shared__ __align__(16) unsigned sB[2][16][264];

    const int b  = blockIdx.z;
    const int o0 = blockIdx.x * 64;
    const int n0 = blockIdx.y * 256;
    const int tid  = threadIdx.x;
    const int wn   = tid >> 5;
    const int lane = tid & 31;
    const int gid = lane >> 2, tig = lane & 3;

    const float* Cb  = g_bcdt2 + (size_t)(b * O3 + 64) * NN;
    const float* h4b = g_h4 + (size_t)b * CC * SS;

    float acc[4][4][4];
#pragma unroll
    for (int i = 0; i < 4; i++)
#pragma unroll
        for (int j = 0; j < 4; j++)
#pragma unroll
            for (int k = 0; k < 4; k++) acc[i][j][k] = 0.f;

    const int ao = tid >> 2, akq = tid & 3;
    const int colA = ao ^ (akq << 3);
    float4 ra, rb[4];

    auto ldg = [&](int s0) {
        ra = *(const float4*)&h4b[(o0 + ao) * SS + s0 + akq * 4];
#pragma unroll
        for (int t = 0; t < 4; t++) {
            int idx = tid + t * 256;
            rb[t] = *(const float4*)&Cb[(size_t)(s0 + (idx >> 6)) * NN + n0 + (idx & 63) * 4];
        }
    };
    auto sts = [&](int st) {
        sA[st][akq * 4 + 0][colA] = f2tf32(ra.x);
        sA[st][akq * 4 + 1][colA] = f2tf32(ra.y);
        sA[st][akq * 4 + 2][colA] = f2tf32(ra.z);
        sA[st][akq * 4 + 3][colA] = f2tf32(ra.w);
#pragma unroll
        for (int t = 0; t < 4; t++) {
            int idx = tid + t * 256;
            uint4 v = {f2tf32(rb[t].x), f2tf32(rb[t].y), f2tf32(rb[t].z), f2tf32(rb[t].w)};
            *(uint4*)&sB[st][idx >> 6][(idx & 63) * 4] = v;
        }
    };
    auto compute = [&](int st) {
#pragma unroll
        for (int ks = 0; ks < 2; ks++) {
            const int r0 = ks * 8 + tig, r1 = r0 + 4;
            unsigned afr[4][4], bfr[4][2];
#pragma unroll
            for (int mt = 0; mt < 4; mt++) {
                int m = mt * 16 + gid;
                afr[mt][0] = sA[st][r0][SWZ(m, r0)];
                afr[mt][1] = sA[st][r0][SWZ(m + 8, r0)];
                afr[mt][2] = sA[st][r1][SWZ(m, r1)];
                afr[mt][3] = sA[st][r1][SWZ(m + 8, r1)];
            }
#pragma unroll
            for (int nt = 0; nt < 4; nt++) {
                int n = wn * 32 + nt * 8 + gid;
                bfr[nt][0] = sB[st][r0][n];
                bfr[nt][1] = sB[st][r1][n];
            }
#pragma unroll
            for (int mt = 0; mt < 4; mt++)
#pragma unroll
                for (int nt = 0; nt < 4; nt++)
                    mma_tf32(acc[mt][nt], afr[mt], bfr[nt]);
        }
    };

    ldg(0); sts(0); __syncthreads();
#pragma unroll 1
    for (int ch = 0; ch < 4; ch++) {
        int st = ch & 1;
        if (ch < 3) ldg((ch + 1) * 16);
        compute(st);
        if (ch < 3) sts(st ^ 1);
        __syncthreads();
    }

#pragma unroll
    for (int mt = 0; mt < 4; mt++) {
        int o = o0 + mt * 16 + gid;
#pragma unroll
        for (int nt = 0; nt < 4; nt++) {
            int n = n0 + wn * 32 + nt * 8 + tig * 2;
            float2 v0 = {acc[mt][nt][0], acc[mt][nt][1]};
            float2 v1 = {acc[mt][nt][2], acc[mt][nt][3]};
            *(float2*)&y[(size_t)(b * CC + o) * NN + n] = v0;
            *(float2*)&y[(size_t)(b * CC + o + 8) * NN + n] = v1;
        }
    }
}

// ============================================================
extern "C" void kernel_launch(void* const* d_in, const int* in_sizes, int n_in,
                              void* d_out, int out_size)
{
    const float* x      = (const float*)d_in[0];
    const float* W_bcdt = (const float*)d_in[1];
    const float* b_bcdt = (const float*)d_in[2];
    const float* W_dw   = (const float*)d_in[3];
    const float* b_dw   = (const float*)d_in[4];
    const float* W_hz   = (const float*)d_in[5];
    const float* b_hz   = (const float*)d_in[6];
    const float* W_out  = (const float*)d_in[7];
    const float* b_out  = (const float*)d_in[8];
    // d_in[9] = A : softmax shift-invariant, cancels exactly
    const float* Dp     = (const float*)d_in[10];
    float* out = (float*)d_out;
    float* out_h4 = out + (size_t)BB * CC * NN;   // y (B,C,D,H,W) then h4 (B,C,S)

    t1_bcdt      <<<dim3(O3 / 64, NN / 256, BB), 256>>>(x, W_bcdt, b_bcdt);
    k2_dwconv    <<<dim3(HH / 4, DD / 4, BB * O3), 256>>>(W_dw, b_dw);
    k3_red       <<<BB * SS, 64>>>();
    t4_h_partial <<<dim3(NSPLIT, 1, BB), 256>>>(x);
    k5_small     <<<BB * SS, 256>>>(W_hz, b_hz, W_out, b_out, Dp, out_h4);
    t6_y         <<<dim3(CC / 64, NN / 256, BB), 256>>>(out);
}